// round 9
// baseline (speedup 1.0000x reference)
#include <cuda_runtime.h>
#include <cuda_fp16.h>
#include <math.h>
#include <stdint.h>

// Problem constants
#define BB 8
#define SS 2048
#define DD 512
#define MFULL (BB * SS)          // 16384
#define INV_T (1.0f / 22.627416997969522f)
#define LN_EPS 1e-5f

// GEMM tiling: 128x256 block tile, warp tile 64x64 (2m x 4n), K-slab 64,
// 4-stage cp.async pipeline, ldmatrix fragments.
#define Bb 128
#define BN 256
#define TKS 64
#define NSTAGE 4
#define RS 72                                  // row stride in halves (64 + 8 pad)
#define TILE_A_HALVES (Bb * RS)                // 9216
#define TILE_B_HALVES (BN * RS)                // 18432
#define STAGE_HALVES (TILE_A_HALVES + TILE_B_HALVES)   // 27648
#define GEMM_SMEM_BYTES (NSTAGE * STAGE_HALVES * 2)    // 221184

// ---------------------------------------------------------------------------
// Scratch (device globals; no allocations allowed)
// ---------------------------------------------------------------------------
__device__ __half g_qh[MFULL * DD];
__device__ __half g_kh[MFULL * DD];
__device__ __half g_t1[MFULL * DD];
__device__ __half g_t2[MFULL * DD];
__device__ __half g_dq[MFULL * DD];
__device__ __half g_dk[MFULL * DD];
__device__ __half g_wt[6 * DD * DD];
__device__ __half g_vt[BB * DD * SS];
__device__ __half g_ah[(long long)BB * SS * SS];
__device__ int    g_mask_is_i32;

// ---------------------------------------------------------------------------
// helpers
// ---------------------------------------------------------------------------
__device__ __forceinline__ uint32_t smem_u32(const void* p) {
    uint32_t a;
    asm("{ .reg .u64 t; cvta.to.shared.u64 t, %1; cvt.u32.u64 %0, t; }" : "=r"(a) : "l"(p));
    return a;
}

__device__ __forceinline__ void mma_f16(float4& d,
    uint32_t a0, uint32_t a1, uint32_t a2, uint32_t a3,
    uint32_t b0, uint32_t b1)
{
    asm volatile(
        "mma.sync.aligned.m16n8k16.row.col.f32.f16.f16.f32 "
        "{%0,%1,%2,%3}, {%4,%5,%6,%7}, {%8,%9}, {%0,%1,%2,%3};\n"
        : "+f"(d.x), "+f"(d.y), "+f"(d.z), "+f"(d.w)
        : "r"(a0), "r"(a1), "r"(a2), "r"(a3), "r"(b0), "r"(b1));
}

#define LDMATRIX_X4(r0, r1, r2, r3, addr) \
    asm volatile("ldmatrix.sync.aligned.m8n8.x4.shared.b16 {%0,%1,%2,%3}, [%4];" \
        : "=r"(r0), "=r"(r1), "=r"(r2), "=r"(r3) : "r"(addr))

#define CP_ASYNC16(dst_u32, src_ptr) \
    asm volatile("cp.async.cg.shared.global [%0], [%1], 16;" \
        :: "r"(dst_u32), "l"(src_ptr) : "memory")
#define CP_COMMIT() asm volatile("cp.async.commit_group;" ::: "memory")
#define CP_WAIT(n)  asm volatile("cp.async.wait_group %0;" :: "n"(n) : "memory")

// ---------------------------------------------------------------------------
// Mask dtype detector
// ---------------------------------------------------------------------------
__global__ void detect_mask_kernel(const unsigned char* __restrict__ mb) {
    __shared__ int any;
    if (threadIdx.x == 0) any = 0;
    __syncthreads();
    for (int i = threadIdx.x; i < 4096; i += blockDim.x) {
        if ((i & 3) && mb[i]) atomicOr(&any, 1);
    }
    __syncthreads();
    if (threadIdx.x == 0) g_mask_is_i32 = any ? 0 : 1;
}

// ---------------------------------------------------------------------------
// fp32 -> fp16 elementwise convert (4 per thread)
// ---------------------------------------------------------------------------
__global__ void convert_h_kernel(const float* __restrict__ S, __half* __restrict__ D,
                                 long long n4) {
    const long long idx = (long long)blockIdx.x * blockDim.x + threadIdx.x;
    if (idx >= n4) return;
    const long long i = idx * 4;
    const float4 v = *(const float4*)(S + i);
    *(__half2*)(D + i)     = __floats2half2_rn(v.x, v.y);
    *(__half2*)(D + i + 2) = __floats2half2_rn(v.z, v.w);
}

// ---------------------------------------------------------------------------
// Tiled transpose with fp16 output: src fp32 [R][C] -> dst half [C][R]
// ---------------------------------------------------------------------------
__global__ void transpose_h_kernel(const float* __restrict__ S, __half* __restrict__ D,
                                   int R, int C, long long sS, long long sD) {
    __shared__ float tile[32][33];
    const float* s = S + (long long)blockIdx.z * sS;
    __half* d = D + (long long)blockIdx.z * sD;
    const int x = blockIdx.x * 32 + threadIdx.x;
    const int y0 = blockIdx.y * 32;
    #pragma unroll
    for (int i = threadIdx.y; i < 32; i += 8)
        tile[i][threadIdx.x] = s[(long long)(y0 + i) * C + x];
    __syncthreads();
    const int xo = blockIdx.y * 32 + threadIdx.x;
    const int yo0 = blockIdx.x * 32;
    #pragma unroll
    for (int i = threadIdx.y; i < 32; i += 8)
        d[(long long)(yo0 + i) * R + xo] = __float2half_rn(tile[threadIdx.x][i]);
}

// ===========================================================================
// Multistage fp16 mma.sync NT GEMM (fp32 accumulate), big tiles:
//   C[m,n] = epilogue( sum_k A[m,k] * B[n,k] )
// A: half [M][K], B: half [N][K]. Block tile 128x256, 256 thr, 8 warps
// (2m x 4n), warp tile 64x64. K-slab 64, 4-stage cp.async, ldmatrix frags.
// EPI: 0 = +bias+relu (half out), 1 = +bias (half out),
//      2 = QK mask/scale (float out), 3 = plain (float out)
// ===========================================================================
template<int EPI>
__global__ void __launch_bounds__(256, 1) gemm_h(
    const __half* __restrict__ Ag, const __half* __restrict__ Bg,
    const float* __restrict__ bias, void* __restrict__ Cg,
    int K, int ldc, long long sA, long long sB, long long sC,
    const void* __restrict__ maskp)
{
    extern __shared__ __half smh[];
    const uint32_t sbase = smem_u32(smh);
    const int tid  = threadIdx.x;
    const int warp = tid >> 5;
    const int lane = tid & 31;
    const int wm = (warp >> 2) * 64;   // 2 m-warps
    const int wn = (warp & 3) * 64;    // 4 n-warps

    const __half* A = Ag + (long long)blockIdx.z * sA;
    const __half* B = Bg + (long long)blockIdx.z * sB;
    const int bm = blockIdx.y * Bb;
    const int bn = blockIdx.x * BN;

    // ldmatrix per-lane source row/col within a 16x16 tile group
    const int lm_row = (lane & 7) + ((lane >> 3) & 1) * 8;
    const int lm_col = ((lane >> 4) & 1) * 8;
    uint32_t offA[4], offB[4];
    #pragma unroll
    for (int i = 0; i < 4; i++)
        offA[i] = (uint32_t)((wm + i * 16 + lm_row) * RS + lm_col);
    #pragma unroll
    for (int j2 = 0; j2 < 4; j2++)
        offB[j2] = (uint32_t)(TILE_A_HALVES + (wn + j2 * 16 + lm_row) * RS + lm_col);

    // cp.async loader: A 128x8 + B 256x8 = 3072 16B-chunks; 12 per thread.
    auto load_stage = [&](int t, int buf) {
        const __half* Abase = A + (long long)bm * K + t * TKS;
        const __half* Bbase = B + (long long)bn * K + t * TKS;
        const uint32_t s0 = sbase + (uint32_t)(buf * STAGE_HALVES) * 2u;
        #pragma unroll
        for (int i = 0; i < 4; i++) {           // A chunks: c in [0,1024)
            const int c = tid + i * 256;
            const int m = c >> 3, kc = c & 7;
            CP_ASYNC16(s0 + (uint32_t)(m * RS + kc * 8) * 2u,
                       Abase + (long long)m * K + kc * 8);
        }
        #pragma unroll
        for (int i = 0; i < 8; i++) {           // B chunks: 2048
            const int c = tid + i * 256;
            const int m = c >> 3, kc = c & 7;
            CP_ASYNC16(s0 + (uint32_t)(TILE_B_HALVES * 0 + TILE_A_HALVES + m * RS + kc * 8) * 2u,
                       Bbase + (long long)m * K + kc * 8);
        }
    };

    float4 acc[4][8];
    #pragma unroll
    for (int i = 0; i < 4; i++)
        #pragma unroll
        for (int j = 0; j < 8; j++) acc[i][j] = make_float4(0.f, 0.f, 0.f, 0.f);

    const int T = K / TKS;

    load_stage(0, 0); CP_COMMIT();
    load_stage(1, 1); CP_COMMIT();
    load_stage(2, 2); CP_COMMIT();

    for (int t = 0; t < T; t++) {
        const int buf = t & 3;
        CP_WAIT(2);                 // stage t resident
        __syncthreads();            // orders compute(t-1) before buf reuse by load(t+3)
        if (t + 3 < T) load_stage(t + 3, (t + 3) & 3);
        CP_COMMIT();                // uniform group accounting

        const uint32_t base = sbase + (uint32_t)(buf * STAGE_HALVES) * 2u;

        #pragma unroll
        for (int ks = 0; ks < 4; ks++) {
            const uint32_t ck2 = (uint32_t)(ks * 16) * 2u;
            uint32_t af[4][4];
            #pragma unroll
            for (int i = 0; i < 4; i++)
                LDMATRIX_X4(af[i][0], af[i][1], af[i][2], af[i][3],
                            base + offA[i] * 2u + ck2);
            #pragma unroll
            for (int j2 = 0; j2 < 4; j2++) {
                uint32_t m0, m1, m2, m3;
                LDMATRIX_X4(m0, m1, m2, m3, base + offB[j2] * 2u + ck2);
                const int j = j2 * 2;
                #pragma unroll
                for (int i = 0; i < 4; i++) {
                    mma_f16(acc[i][j],     af[i][0], af[i][1], af[i][2], af[i][3], m0, m2);
                    mma_f16(acc[i][j + 1], af[i][0], af[i][1], af[i][2], af[i][3], m1, m3);
                }
            }
        }
    }

    // Epilogue
    const int is_i32 = (EPI == 2) ? g_mask_is_i32 : 0;
    #pragma unroll
    for (int i = 0; i < 4; i++) {
        const int r0 = bm + wm + i * 16 + (lane >> 2);
        const int r1 = r0 + 8;
        #pragma unroll
        for (int j = 0; j < 8; j++) {
            const int c = bn + wn + j * 8 + (lane & 3) * 2;
            float2 v0 = make_float2(acc[i][j].x, acc[i][j].y);
            float2 v1 = make_float2(acc[i][j].z, acc[i][j].w);
            if (EPI == 0 || EPI == 1) {
                const float2 b = *(const float2*)(bias + c);
                v0.x += b.x; v0.y += b.y;
                v1.x += b.x; v1.y += b.y;
                if (EPI == 0) {
                    v0.x = fmaxf(v0.x, 0.f); v0.y = fmaxf(v0.y, 0.f);
                    v1.x = fmaxf(v1.x, 0.f); v1.y = fmaxf(v1.y, 0.f);
                }
                __half* C = (__half*)Cg + (long long)blockIdx.z * sC;
                *(__half2*)(C + (long long)r0 * ldc + c) = __floats2half2_rn(v0.x, v0.y);
                *(__half2*)(C + (long long)r1 * ldc + c) = __floats2half2_rn(v1.x, v1.y);
            } else {
                if (EPI == 2) {
                    const long long base2 = (long long)blockIdx.z * SS * SS;
                    const long long i00 = base2 + (long long)r0 * SS + c;
                    const long long i10 = base2 + (long long)r1 * SS + c;
                    bool m00, m01, m10, m11;
                    if (is_i32) {
                        const int* mi = (const int*)maskp;
                        m00 = mi[i00] != 0; m01 = mi[i00 + 1] != 0;
                        m10 = mi[i10] != 0; m11 = mi[i10 + 1] != 0;
                    } else {
                        const unsigned char* mu = (const unsigned char*)maskp;
                        m00 = mu[i00] != 0; m01 = mu[i00 + 1] != 0;
                        m10 = mu[i10] != 0; m11 = mu[i10 + 1] != 0;
                    }
                    v0.x = m00 ? -1e16f : v0.x * INV_T;
                    v0.y = m01 ? -1e16f : v0.y * INV_T;
                    v1.x = m10 ? -1e16f : v1.x * INV_T;
                    v1.y = m11 ? -1e16f : v1.y * INV_T;
                }
                float* C = (float*)Cg + (long long)blockIdx.z * sC;
                *(float2*)(C + (long long)r0 * ldc + c) = v0;
                *(float2*)(C + (long long)r1 * ldc + c) = v1;
            }
        }
    }
}

// ---------------------------------------------------------------------------
// Block reductions
// ---------------------------------------------------------------------------
__device__ __forceinline__ float blockReduceSum(float v, float* sh) {
    #pragma unroll
    for (int o = 16; o > 0; o >>= 1) v += __shfl_xor_sync(0xffffffffu, v, o);
    __syncthreads();
    if ((threadIdx.x & 31) == 0) sh[threadIdx.x >> 5] = v;
    __syncthreads();
    if (threadIdx.x < 32) {
        v = (threadIdx.x < (blockDim.x >> 5)) ? sh[threadIdx.x] : 0.0f;
        #pragma unroll
        for (int o = 16; o > 0; o >>= 1) v += __shfl_xor_sync(0xffffffffu, v, o);
        if (threadIdx.x == 0) sh[0] = v;
    }
    __syncthreads();
    return sh[0];
}

__device__ __forceinline__ float blockReduceMax(float v, float* sh) {
    #pragma unroll
    for (int o = 16; o > 0; o >>= 1) v = fmaxf(v, __shfl_xor_sync(0xffffffffu, v, o));
    __syncthreads();
    if ((threadIdx.x & 31) == 0) sh[threadIdx.x >> 5] = v;
    __syncthreads();
    if (threadIdx.x < 32) {
        v = (threadIdx.x < (blockDim.x >> 5)) ? sh[threadIdx.x] : -3.0e38f;
        #pragma unroll
        for (int o = 16; o > 0; o >>= 1) v = fmaxf(v, __shfl_xor_sync(0xffffffffu, v, o));
        if (threadIdx.x == 0) sh[0] = v;
    }
    __syncthreads();
    return sh[0];
}

// ---------------------------------------------------------------------------
// LayerNorm + ReLU: half in, half out (stats in fp32)
// ---------------------------------------------------------------------------
__global__ void ln_relu_h_kernel(const __half* __restrict__ X,
                                 const float* __restrict__ g,
                                 const float* __restrict__ beta,
                                 __half* __restrict__ Y)
{
    __shared__ float sh[32];
    const long long row = blockIdx.x;
    const __half* x = X + row * DD;
    const int t = threadIdx.x;

    const __half2 h0 = *(const __half2*)(x + t * 4);
    const __half2 h1 = *(const __half2*)(x + t * 4 + 2);
    const float2 f0 = __half22float2(h0);
    const float2 f1 = __half22float2(h1);
    float s  = f0.x + f0.y + f1.x + f1.y;
    float sq = f0.x * f0.x + f0.y * f0.y + f1.x * f1.x + f1.y * f1.y;
    s  = blockReduceSum(s, sh);
    sq = blockReduceSum(sq, sh);
    const float mu  = s * (1.0f / DD);
    const float var = sq * (1.0f / DD) - mu * mu;
    const float r = rsqrtf(var + LN_EPS);

    const float4 gv = *(const float4*)(g + t * 4);
    const float4 bv = *(const float4*)(beta + t * 4);
    float y0 = fmaxf((f0.x - mu) * r * gv.x + bv.x, 0.0f);
    float y1 = fmaxf((f0.y - mu) * r * gv.y + bv.y, 0.0f);
    float y2 = fmaxf((f1.x - mu) * r * gv.z + bv.z, 0.0f);
    float y3 = fmaxf((f1.y - mu) * r * gv.w + bv.w, 0.0f);
    *(__half2*)(Y + row * DD + t * 4)     = __floats2half2_rn(y0, y1);
    *(__half2*)(Y + row * DD + t * 4 + 2) = __floats2half2_rn(y2, y3);
}

// ---------------------------------------------------------------------------
// Negated softmax over rows of 2048, in place (fp32) + half mirror for PV.
// ---------------------------------------------------------------------------
__global__ void softmax_neg_kernel(float* __restrict__ P, __half* __restrict__ PH) {
    __shared__ float sh[32];
    float* p = P + (long long)blockIdx.x * SS;
    __half* ph = PH + (long long)blockIdx.x * SS;
    const int t = threadIdx.x;

    float4 x0 = *(float4*)(p + t * 8);
    float4 x1 = *(float4*)(p + t * 8 + 4);
    float mx = fmaxf(fmaxf(fmaxf(x0.x, x0.y), fmaxf(x0.z, x0.w)),
                     fmaxf(fmaxf(x1.x, x1.y), fmaxf(x1.z, x1.w)));
    mx = blockReduceMax(mx, sh);

    float e[8];
    e[0] = __expf(x0.x - mx); e[1] = __expf(x0.y - mx);
    e[2] = __expf(x0.z - mx); e[3] = __expf(x0.w - mx);
    e[4] = __expf(x1.x - mx); e[5] = __expf(x1.y - mx);
    e[6] = __expf(x1.z - mx); e[7] = __expf(x1.w - mx);
    float s = e[0] + e[1] + e[2] + e[3] + e[4] + e[5] + e[6] + e[7];
    s = blockReduceSum(s, sh);
    const float inv = -1.0f / s;

    x0.x = e[0] * inv; x0.y = e[1] * inv; x0.z = e[2] * inv; x0.w = e[3] * inv;
    x1.x = e[4] * inv; x1.y = e[5] * inv; x1.z = e[6] * inv; x1.w = e[7] * inv;
    *(float4*)(p + t * 8)     = x0;
    *(float4*)(p + t * 8 + 4) = x1;
    *(__half2*)(ph + t * 8)     = __floats2half2_rn(x0.x, x0.y);
    *(__half2*)(ph + t * 8 + 2) = __floats2half2_rn(x0.z, x0.w);
    *(__half2*)(ph + t * 8 + 4) = __floats2half2_rn(x1.x, x1.y);
    *(__half2*)(ph + t * 8 + 6) = __floats2half2_rn(x1.z, x1.w);
}

// ---------------------------------------------------------------------------
// Launch
// ---------------------------------------------------------------------------
extern "C" void kernel_launch(void* const* d_in, const int* in_sizes, int n_in,
                              void* d_out, int out_size)
{
    const float* q   = (const float*)d_in[0];
    const float* k   = (const float*)d_in[1];
    const float* v   = (const float*)d_in[2];
    const void*  mask = d_in[3];
    const float* qw1 = (const float*)d_in[4];
    const float* qw2 = (const float*)d_in[5];
    const float* qw3 = (const float*)d_in[6];
    const float* kw1 = (const float*)d_in[7];
    const float* kw2 = (const float*)d_in[8];
    const float* kw3 = (const float*)d_in[9];
    const float* qb1 = (const float*)d_in[10];
    const float* qb2 = (const float*)d_in[11];
    const float* qb3 = (const float*)d_in[12];
    const float* kb1 = (const float*)d_in[13];
    const float* kb2 = (const float*)d_in[14];
    const float* kb3 = (const float*)d_in[15];
    const float* q_ln_b = (const float*)d_in[16];
    const float* k_ln_b = (const float*)d_in[17];
    const float* q_ln_g = (const float*)d_in[18];
    const float* k_ln_g = (const float*)d_in[19];

    float* out  = (float*)d_out;                              // [B,S,D]
    float* attn = out + (long long)BB * SS * DD;              // [B,S,S]

    __half *qh, *kh, *t1, *t2, *dq, *dk, *wt, *vt, *ah;
    cudaGetSymbolAddress((void**)&qh, g_qh);
    cudaGetSymbolAddress((void**)&kh, g_kh);
    cudaGetSymbolAddress((void**)&t1, g_t1);
    cudaGetSymbolAddress((void**)&t2, g_t2);
    cudaGetSymbolAddress((void**)&dq, g_dq);
    cudaGetSymbolAddress((void**)&dk, g_dk);
    cudaGetSymbolAddress((void**)&wt, g_wt);
    cudaGetSymbolAddress((void**)&vt, g_vt);
    cudaGetSymbolAddress((void**)&ah, g_ah);

    const size_t shm = GEMM_SMEM_BYTES;
    cudaFuncSetAttribute(gemm_h<0>, cudaFuncAttributeMaxDynamicSharedMemorySize, shm);
    cudaFuncSetAttribute(gemm_h<1>, cudaFuncAttributeMaxDynamicSharedMemorySize, shm);
    cudaFuncSetAttribute(gemm_h<2>, cudaFuncAttributeMaxDynamicSharedMemorySize, shm);
    cudaFuncSetAttribute(gemm_h<3>, cudaFuncAttributeMaxDynamicSharedMemorySize, shm);

    detect_mask_kernel<<<1, 256>>>((const unsigned char*)mask);

    // fp32 -> fp16 inputs
    const long long n4 = (long long)MFULL * DD / 4;
    convert_h_kernel<<<(int)((n4 + 255) / 256), 256>>>(q, qh, n4);
    convert_h_kernel<<<(int)((n4 + 255) / 256), 256>>>(k, kh, n4);

    // Weights W[k][n] -> half Wt[n][k]
    const float* ws[6] = {qw1, qw2, qw3, kw1, kw2, kw3};
    for (int i = 0; i < 6; i++)
        transpose_h_kernel<<<dim3(16, 16, 1), dim3(32, 8)>>>(
            ws[i], wt + (long long)i * DD * DD, DD, DD, 0, 0);
    __half* wtq1 = wt + 0LL * DD * DD; __half* wtq2 = wt + 1LL * DD * DD;
    __half* wtq3 = wt + 2LL * DD * DD; __half* wtk1 = wt + 3LL * DD * DD;
    __half* wtk2 = wt + 4LL * DD * DD; __half* wtk3 = wt + 5LL * DD * DD;

    // V[b][t][d] -> half Vt[b][d][t]
    transpose_h_kernel<<<dim3(DD / 32, SS / 32, BB), dim3(32, 8)>>>(
        v, vt, SS, DD, (long long)SS * DD, (long long)DD * SS);

    const dim3 gMLP(DD / BN, MFULL / Bb, 1);    // (2, 128, 1)

    // ---- deep_q ----
    gemm_h<0><<<gMLP, 256, shm>>>(qh, wtq1, qb1, t1, DD, DD, 0, 0, 0, nullptr);
    gemm_h<1><<<gMLP, 256, shm>>>(t1, wtq2, qb2, t2, DD, DD, 0, 0, 0, nullptr);
    ln_relu_h_kernel<<<MFULL, 128>>>(t2, q_ln_g, q_ln_b, t1);
    gemm_h<1><<<gMLP, 256, shm>>>(t1, wtq3, qb3, dq, DD, DD, 0, 0, 0, nullptr);

    // ---- deep_k ----
    gemm_h<0><<<gMLP, 256, shm>>>(kh, wtk1, kb1, t1, DD, DD, 0, 0, 0, nullptr);
    gemm_h<1><<<gMLP, 256, shm>>>(t1, wtk2, kb2, t2, DD, DD, 0, 0, 0, nullptr);
    ln_relu_h_kernel<<<MFULL, 128>>>(t2, k_ln_g, k_ln_b, t1);
    gemm_h<1><<<gMLP, 256, shm>>>(t1, wtk3, kb3, dk, DD, DD, 0, 0, 0, nullptr);

    // ---- attention ----
    gemm_h<2><<<dim3(SS / BN, SS / Bb, BB), 256, shm>>>(
        dq, dk, nullptr, attn, DD, SS,
        (long long)SS * DD, (long long)SS * DD, (long long)SS * SS, mask);
    softmax_neg_kernel<<<MFULL, 256>>>(attn, ah);
    gemm_h<3><<<dim3(DD / BN, SS / Bb, BB), 256, shm>>>(
        ah, vt, nullptr, out, SS, DD,
        (long long)SS * SS, (long long)DD * SS, (long long)SS * DD, nullptr);
}

// round 10
// speedup vs baseline: 1.1309x; 1.1309x over previous
#include <cuda_runtime.h>
#include <cuda_fp16.h>
#include <math.h>
#include <stdint.h>

// Problem constants
#define BB 8
#define SS 2048
#define DD 512
#define MFULL (BB * SS)          // 16384
#define INV_T (1.0f / 22.627416997969522f)
#define LN_EPS 1e-5f

// GEMM tiling: 128x128 block tile, K-slab 64, 3-stage cp.async, ldmatrix
#define TKS 64
#define NSTAGE 3
#define RS 72                                  // row stride in halves (64 + 8 pad)
#define TILE_HALVES (128 * RS)                 // 9216
#define STAGE_HALVES (2 * TILE_HALVES)         // 18432
#define GEMM_SMEM_BYTES (NSTAGE * STAGE_HALVES * 2)   // 110592

// ---------------------------------------------------------------------------
// Scratch (device globals; no allocations allowed)
// ---------------------------------------------------------------------------
__device__ __half g_qh[MFULL * DD];
__device__ __half g_kh[MFULL * DD];
__device__ __half g_t1[MFULL * DD];
__device__ __half g_t2[MFULL * DD];
__device__ __half g_t3[MFULL * DD];
__device__ __half g_t4[MFULL * DD];
__device__ __half g_dq[MFULL * DD];
__device__ __half g_dk[MFULL * DD];
__device__ __half g_wt[6 * DD * DD];
__device__ __half g_vt[BB * DD * SS];
__device__ __half g_ah[(long long)BB * SS * SS];   // logits, then probs (half)
__device__ int    g_mask_is_i32;

// ---------------------------------------------------------------------------
// helpers
// ---------------------------------------------------------------------------
__device__ __forceinline__ uint32_t smem_u32(const void* p) {
    uint32_t a;
    asm("{ .reg .u64 t; cvta.to.shared.u64 t, %1; cvt.u32.u64 %0, t; }" : "=r"(a) : "l"(p));
    return a;
}

__device__ __forceinline__ void mma_f16(float4& d,
    uint32_t a0, uint32_t a1, uint32_t a2, uint32_t a3,
    uint32_t b0, uint32_t b1)
{
    asm volatile(
        "mma.sync.aligned.m16n8k16.row.col.f32.f16.f16.f32 "
        "{%0,%1,%2,%3}, {%4,%5,%6,%7}, {%8,%9}, {%0,%1,%2,%3};\n"
        : "+f"(d.x), "+f"(d.y), "+f"(d.z), "+f"(d.w)
        : "r"(a0), "r"(a1), "r"(a2), "r"(a3), "r"(b0), "r"(b1));
}

#define LDMATRIX_X4(r0, r1, r2, r3, addr) \
    asm volatile("ldmatrix.sync.aligned.m8n8.x4.shared.b16 {%0,%1,%2,%3}, [%4];" \
        : "=r"(r0), "=r"(r1), "=r"(r2), "=r"(r3) : "r"(addr))

#define CP_ASYNC16(dst_u32, src_ptr) \
    asm volatile("cp.async.cg.shared.global [%0], [%1], 16;" \
        :: "r"(dst_u32), "l"(src_ptr) : "memory")
#define CP_COMMIT() asm volatile("cp.async.commit_group;" ::: "memory")
#define CP_WAIT(n)  asm volatile("cp.async.wait_group %0;" :: "n"(n) : "memory")

// ---------------------------------------------------------------------------
// Mask dtype detector
// ---------------------------------------------------------------------------
__global__ void detect_mask_kernel(const unsigned char* __restrict__ mb) {
    __shared__ int any;
    if (threadIdx.x == 0) any = 0;
    __syncthreads();
    for (int i = threadIdx.x; i < 4096; i += blockDim.x) {
        if ((i & 3) && mb[i]) atomicOr(&any, 1);
    }
    __syncthreads();
    if (threadIdx.x == 0) g_mask_is_i32 = any ? 0 : 1;
}

// ---------------------------------------------------------------------------
// fp32 -> fp16 convert, two tensors in one launch
// ---------------------------------------------------------------------------
__global__ void convert2_h_kernel(const float* __restrict__ S0, __half* __restrict__ D0,
                                  const float* __restrict__ S1, __half* __restrict__ D1,
                                  long long n4) {
    long long idx = (long long)blockIdx.x * blockDim.x + threadIdx.x;
    const float* S; __half* D;
    if (idx < n4) { S = S0; D = D0; }
    else if (idx < 2 * n4) { S = S1; D = D1; idx -= n4; }
    else return;
    const long long i = idx * 4;
    const float4 v = *(const float4*)(S + i);
    *(__half2*)(D + i)     = __floats2half2_rn(v.x, v.y);
    *(__half2*)(D + i + 2) = __floats2half2_rn(v.z, v.w);
}

// ---------------------------------------------------------------------------
// Batched 512x512 weight transpose (6 weights in one launch via z)
// ---------------------------------------------------------------------------
struct WtPtrs { const float* s[6]; };
__global__ void transpose_w6_kernel(WtPtrs ps, __half* __restrict__ Dbase) {
    __shared__ float tile[32][33];
    const float* s = ps.s[blockIdx.z];
    __half* d = Dbase + (long long)blockIdx.z * DD * DD;
    const int x = blockIdx.x * 32 + threadIdx.x;
    const int y0 = blockIdx.y * 32;
    #pragma unroll
    for (int i = threadIdx.y; i < 32; i += 8)
        tile[i][threadIdx.x] = s[(long long)(y0 + i) * DD + x];
    __syncthreads();
    const int xo = blockIdx.y * 32 + threadIdx.x;
    const int yo0 = blockIdx.x * 32;
    #pragma unroll
    for (int i = threadIdx.y; i < 32; i += 8)
        d[(long long)(yo0 + i) * DD + xo] = __float2half_rn(tile[threadIdx.x][i]);
}

// ---------------------------------------------------------------------------
// V transpose: fp32 [b][t][d] -> half [b][d][t]
// ---------------------------------------------------------------------------
__global__ void transpose_v_kernel(const float* __restrict__ S, __half* __restrict__ D) {
    __shared__ float tile[32][33];
    const float* s = S + (long long)blockIdx.z * SS * DD;
    __half* d = D + (long long)blockIdx.z * DD * SS;
    const int x = blockIdx.x * 32 + threadIdx.x;
    const int y0 = blockIdx.y * 32;
    #pragma unroll
    for (int i = threadIdx.y; i < 32; i += 8)
        tile[i][threadIdx.x] = s[(long long)(y0 + i) * DD + x];
    __syncthreads();
    const int xo = blockIdx.y * 32 + threadIdx.x;
    const int yo0 = blockIdx.x * 32;
    #pragma unroll
    for (int i = threadIdx.y; i < 32; i += 8)
        d[(long long)(yo0 + i) * SS + xo] = __float2half_rn(tile[threadIdx.x][i]);
}

// ===========================================================================
// Multistage fp16 mma.sync NT GEMM (fp32 accumulate), ldmatrix fragments.
//   C[m,n] = epilogue( sum_k A[m,k] * B[n,k] )
// Block tile 128x128, 256 thr, 8 warps (4m x 2n), warp tile 32x64.
// DUAL: blockIdx.z selects pointer set 0/1 (independent problems, strides 0).
// !DUAL: blockIdx.z batches via sA/sB/sC element strides.
// EPI: 0 = +bias+relu (half out), 1 = +bias (half out),
//      2 = QK mask/scale (HALF out), 3 = plain (float out)
// ===========================================================================
template<int EPI, bool DUAL>
__global__ void __launch_bounds__(256, 2) gemm_h(
    const __half* __restrict__ A0, const __half* __restrict__ B0,
    const float* __restrict__ bias0, void* __restrict__ C0,
    const __half* __restrict__ A1, const __half* __restrict__ B1,
    const float* __restrict__ bias1, void* __restrict__ C1,
    int K, int ldc, long long sA, long long sB, long long sC,
    const void* __restrict__ maskp)
{
    extern __shared__ __half smh[];
    const uint32_t sbase = smem_u32(smh);
    const int tid  = threadIdx.x;
    const int warp = tid >> 5;
    const int lane = tid & 31;
    const int wm = (warp >> 1) * 32;
    const int wn = (warp & 1) * 64;
    const int z = blockIdx.z;

    const __half* A; const __half* B; const float* bias; void* Cg;
    if (DUAL && z == 1) { A = A1; B = B1; bias = bias1; Cg = C1; }
    else {
        A = A0 + (long long)z * sA;
        B = B0 + (long long)z * sB;
        bias = bias0; Cg = C0;
    }
    const long long csoff = DUAL ? 0 : (long long)z * sC;

    const int bm = blockIdx.y * 128;
    const int bn = blockIdx.x * 128;

    const int lm_row = (lane & 7) + ((lane >> 3) & 1) * 8;
    const int lm_col = ((lane >> 4) & 1) * 8;
    uint32_t offA[2], offB[4];
    #pragma unroll
    for (int i = 0; i < 2; i++)
        offA[i] = (uint32_t)((wm + i * 16 + lm_row) * RS + lm_col);
    #pragma unroll
    for (int j2 = 0; j2 < 4; j2++)
        offB[j2] = (uint32_t)(TILE_HALVES + (wn + j2 * 16 + lm_row) * RS + lm_col);

    auto load_stage = [&](int t, int buf) {
        const __half* Abase = A + (long long)bm * K + t * TKS;
        const __half* Bbase = B + (long long)bn * K + t * TKS;
        const uint32_t s0 = sbase + (uint32_t)(buf * STAGE_HALVES) * 2u;
        #pragma unroll
        for (int i = 0; i < 4; i++) {
            const int c = tid + i * 256;
            const int m = c >> 3, kc = c & 7;
            CP_ASYNC16(s0 + (uint32_t)(m * RS + kc * 8) * 2u,
                       Abase + (long long)m * K + kc * 8);
            CP_ASYNC16(s0 + (uint32_t)(TILE_HALVES + m * RS + kc * 8) * 2u,
                       Bbase + (long long)m * K + kc * 8);
        }
    };

    float4 acc[2][8];
    #pragma unroll
    for (int i = 0; i < 2; i++)
        #pragma unroll
        for (int j = 0; j < 8; j++) acc[i][j] = make_float4(0.f, 0.f, 0.f, 0.f);

    const int T = K / TKS;

    load_stage(0, 0); CP_COMMIT();
    load_stage(1, 1); CP_COMMIT();

    for (int t = 0; t < T; t++) {
        const int buf = t % NSTAGE;
        CP_WAIT(1);
        __syncthreads();
        if (t + 2 < T) load_stage(t + 2, (t + 2) % NSTAGE);
        CP_COMMIT();

        const uint32_t base = sbase + (uint32_t)(buf * STAGE_HALVES) * 2u;

        #pragma unroll
        for (int ks = 0; ks < 4; ks++) {
            const uint32_t ck2 = (uint32_t)(ks * 16) * 2u;
            uint32_t af[2][4];
            LDMATRIX_X4(af[0][0], af[0][1], af[0][2], af[0][3], base + offA[0] * 2u + ck2);
            LDMATRIX_X4(af[1][0], af[1][1], af[1][2], af[1][3], base + offA[1] * 2u + ck2);
            #pragma unroll
            for (int j2 = 0; j2 < 4; j2++) {
                uint32_t m0, m1, m2, m3;
                LDMATRIX_X4(m0, m1, m2, m3, base + offB[j2] * 2u + ck2);
                const int j = j2 * 2;
                mma_f16(acc[0][j],     af[0][0], af[0][1], af[0][2], af[0][3], m0, m2);
                mma_f16(acc[1][j],     af[1][0], af[1][1], af[1][2], af[1][3], m0, m2);
                mma_f16(acc[0][j + 1], af[0][0], af[0][1], af[0][2], af[0][3], m1, m3);
                mma_f16(acc[1][j + 1], af[1][0], af[1][1], af[1][2], af[1][3], m1, m3);
            }
        }
    }

    // Epilogue
    const int is_i32 = (EPI == 2) ? g_mask_is_i32 : 0;
    #pragma unroll
    for (int i = 0; i < 2; i++) {
        const int r0 = bm + wm + i * 16 + (lane >> 2);
        const int r1 = r0 + 8;
        #pragma unroll
        for (int j = 0; j < 8; j++) {
            const int c = bn + wn + j * 8 + (lane & 3) * 2;
            float2 v0 = make_float2(acc[i][j].x, acc[i][j].y);
            float2 v1 = make_float2(acc[i][j].z, acc[i][j].w);
            if (EPI == 0 || EPI == 1) {
                const float2 b = *(const float2*)(bias + c);
                v0.x += b.x; v0.y += b.y;
                v1.x += b.x; v1.y += b.y;
                if (EPI == 0) {
                    v0.x = fmaxf(v0.x, 0.f); v0.y = fmaxf(v0.y, 0.f);
                    v1.x = fmaxf(v1.x, 0.f); v1.y = fmaxf(v1.y, 0.f);
                }
                __half* C = (__half*)Cg + csoff;
                *(__half2*)(C + (long long)r0 * ldc + c) = __floats2half2_rn(v0.x, v0.y);
                *(__half2*)(C + (long long)r1 * ldc + c) = __floats2half2_rn(v1.x, v1.y);
            } else if (EPI == 2) {
                const long long base2 = (long long)z * SS * SS;
                const long long i00 = base2 + (long long)r0 * SS + c;
                const long long i10 = base2 + (long long)r1 * SS + c;
                bool m00, m01, m10, m11;
                if (is_i32) {
                    const int* mi = (const int*)maskp;
                    m00 = mi[i00] != 0; m01 = mi[i00 + 1] != 0;
                    m10 = mi[i10] != 0; m11 = mi[i10 + 1] != 0;
                } else {
                    const unsigned char* mu = (const unsigned char*)maskp;
                    m00 = mu[i00] != 0; m01 = mu[i00 + 1] != 0;
                    m10 = mu[i10] != 0; m11 = mu[i10 + 1] != 0;
                }
                v0.x = m00 ? -60000.f : v0.x * INV_T;
                v0.y = m01 ? -60000.f : v0.y * INV_T;
                v1.x = m10 ? -60000.f : v1.x * INV_T;
                v1.y = m11 ? -60000.f : v1.y * INV_T;
                __half* C = (__half*)Cg + csoff;
                *(__half2*)(C + (long long)r0 * ldc + c) = __floats2half2_rn(v0.x, v0.y);
                *(__half2*)(C + (long long)r1 * ldc + c) = __floats2half2_rn(v1.x, v1.y);
            } else {
                float* C = (float*)Cg + csoff;
                *(float2*)(C + (long long)r0 * ldc + c) = v0;
                *(float2*)(C + (long long)r1 * ldc + c) = v1;
            }
        }
    }
}

// ---------------------------------------------------------------------------
// Block reductions
// ---------------------------------------------------------------------------
__device__ __forceinline__ float blockReduceSum(float v, float* sh) {
    #pragma unroll
    for (int o = 16; o > 0; o >>= 1) v += __shfl_xor_sync(0xffffffffu, v, o);
    __syncthreads();
    if ((threadIdx.x & 31) == 0) sh[threadIdx.x >> 5] = v;
    __syncthreads();
    if (threadIdx.x < 32) {
        v = (threadIdx.x < (blockDim.x >> 5)) ? sh[threadIdx.x] : 0.0f;
        #pragma unroll
        for (int o = 16; o > 0; o >>= 1) v += __shfl_xor_sync(0xffffffffu, v, o);
        if (threadIdx.x == 0) sh[0] = v;
    }
    __syncthreads();
    return sh[0];
}

__device__ __forceinline__ float blockReduceMax(float v, float* sh) {
    #pragma unroll
    for (int o = 16; o > 0; o >>= 1) v = fmaxf(v, __shfl_xor_sync(0xffffffffu, v, o));
    __syncthreads();
    if ((threadIdx.x & 31) == 0) sh[threadIdx.x >> 5] = v;
    __syncthreads();
    if (threadIdx.x < 32) {
        v = (threadIdx.x < (blockDim.x >> 5)) ? sh[threadIdx.x] : -3.0e38f;
        #pragma unroll
        for (int o = 16; o > 0; o >>= 1) v = fmaxf(v, __shfl_xor_sync(0xffffffffu, v, o));
        if (threadIdx.x == 0) sh[0] = v;
    }
    __syncthreads();
    return sh[0];
}

// ---------------------------------------------------------------------------
// LayerNorm + ReLU, dual chain in one launch (q rows then k rows)
// ---------------------------------------------------------------------------
__global__ void ln_relu_h2_kernel(const __half* __restrict__ X0, __half* __restrict__ Y0,
                                  const float* __restrict__ g0, const float* __restrict__ b0,
                                  const __half* __restrict__ X1, __half* __restrict__ Y1,
                                  const float* __restrict__ g1, const float* __restrict__ b1)
{
    __shared__ float sh[32];
    long long row = blockIdx.x;
    const __half* X; __half* Y; const float* g; const float* beta;
    if (row < MFULL) { X = X0; Y = Y0; g = g0; beta = b0; }
    else { row -= MFULL; X = X1; Y = Y1; g = g1; beta = b1; }
    const __half* x = X + row * DD;
    const int t = threadIdx.x;

    const __half2 h0 = *(const __half2*)(x + t * 4);
    const __half2 h1 = *(const __half2*)(x + t * 4 + 2);
    const float2 f0 = __half22float2(h0);
    const float2 f1 = __half22float2(h1);
    float s  = f0.x + f0.y + f1.x + f1.y;
    float sq = f0.x * f0.x + f0.y * f0.y + f1.x * f1.x + f1.y * f1.y;
    s  = blockReduceSum(s, sh);
    sq = blockReduceSum(sq, sh);
    const float mu  = s * (1.0f / DD);
    const float var = sq * (1.0f / DD) - mu * mu;
    const float r = rsqrtf(var + LN_EPS);

    const float4 gv = *(const float4*)(g + t * 4);
    const float4 bv = *(const float4*)(beta + t * 4);
    float y0 = fmaxf((f0.x - mu) * r * gv.x + bv.x, 0.0f);
    float y1 = fmaxf((f0.y - mu) * r * gv.y + bv.y, 0.0f);
    float y2 = fmaxf((f1.x - mu) * r * gv.z + bv.z, 0.0f);
    float y3 = fmaxf((f1.y - mu) * r * gv.w + bv.w, 0.0f);
    *(__half2*)(Y + row * DD + t * 4)     = __floats2half2_rn(y0, y1);
    *(__half2*)(Y + row * DD + t * 4 + 2) = __floats2half2_rn(y2, y3);
}

// ---------------------------------------------------------------------------
// Negated softmax: reads half logits (in place), writes fp32 attn + half probs
// ---------------------------------------------------------------------------
__global__ void softmax_neg_kernel(__half* __restrict__ PH, float* __restrict__ P) {
    __shared__ float sh[32];
    __half* ph = PH + (long long)blockIdx.x * SS;
    float* p = P + (long long)blockIdx.x * SS;
    const int t = threadIdx.x;

    const __half2 h0 = *(__half2*)(ph + t * 8);
    const __half2 h1 = *(__half2*)(ph + t * 8 + 2);
    const __half2 h2 = *(__half2*)(ph + t * 8 + 4);
    const __half2 h3 = *(__half2*)(ph + t * 8 + 6);
    const float2 a = __half22float2(h0);
    const float2 b = __half22float2(h1);
    const float2 c = __half22float2(h2);
    const float2 d = __half22float2(h3);
    float x[8] = {a.x, a.y, b.x, b.y, c.x, c.y, d.x, d.y};

    float mx = x[0];
    #pragma unroll
    for (int i = 1; i < 8; i++) mx = fmaxf(mx, x[i]);
    mx = blockReduceMax(mx, sh);

    float e[8], s = 0.f;
    #pragma unroll
    for (int i = 0; i < 8; i++) { e[i] = __expf(x[i] - mx); s += e[i]; }
    s = blockReduceSum(s, sh);
    const float inv = -1.0f / s;

    #pragma unroll
    for (int i = 0; i < 8; i++) e[i] *= inv;
    *(float4*)(p + t * 8)     = make_float4(e[0], e[1], e[2], e[3]);
    *(float4*)(p + t * 8 + 4) = make_float4(e[4], e[5], e[6], e[7]);
    *(__half2*)(ph + t * 8)     = __floats2half2_rn(e[0], e[1]);
    *(__half2*)(ph + t * 8 + 2) = __floats2half2_rn(e[2], e[3]);
    *(__half2*)(ph + t * 8 + 4) = __floats2half2_rn(e[4], e[5]);
    *(__half2*)(ph + t * 8 + 6) = __floats2half2_rn(e[6], e[7]);
}

// ---------------------------------------------------------------------------
// Launch
// ---------------------------------------------------------------------------
extern "C" void kernel_launch(void* const* d_in, const int* in_sizes, int n_in,
                              void* d_out, int out_size)
{
    const float* q   = (const float*)d_in[0];
    const float* k   = (const float*)d_in[1];
    const float* v   = (const float*)d_in[2];
    const void*  mask = d_in[3];
    const float* qw1 = (const float*)d_in[4];
    const float* qw2 = (const float*)d_in[5];
    const float* qw3 = (const float*)d_in[6];
    const float* kw1 = (const float*)d_in[7];
    const float* kw2 = (const float*)d_in[8];
    const float* kw3 = (const float*)d_in[9];
    const float* qb1 = (const float*)d_in[10];
    const float* qb2 = (const float*)d_in[11];
    const float* qb3 = (const float*)d_in[12];
    const float* kb1 = (const float*)d_in[13];
    const float* kb2 = (const float*)d_in[14];
    const float* kb3 = (const float*)d_in[15];
    const float* q_ln_b = (const float*)d_in[16];
    const float* k_ln_b = (const float*)d_in[17];
    const float* q_ln_g = (const float*)d_in[18];
    const float* k_ln_g = (const float*)d_in[19];

    float* out  = (float*)d_out;                              // [B,S,D]
    float* attn = out + (long long)BB * SS * DD;              // [B,S,S]

    __half *qh, *kh, *t1, *t2, *t3, *t4, *dq, *dk, *wt, *vt, *ah;
    cudaGetSymbolAddress((void**)&qh, g_qh);
    cudaGetSymbolAddress((void**)&kh, g_kh);
    cudaGetSymbolAddress((void**)&t1, g_t1);
    cudaGetSymbolAddress((void**)&t2, g_t2);
    cudaGetSymbolAddress((void**)&t3, g_t3);
    cudaGetSymbolAddress((void**)&t4, g_t4);
    cudaGetSymbolAddress((void**)&dq, g_dq);
    cudaGetSymbolAddress((void**)&dk, g_dk);
    cudaGetSymbolAddress((void**)&wt, g_wt);
    cudaGetSymbolAddress((void**)&vt, g_vt);
    cudaGetSymbolAddress((void**)&ah, g_ah);

    const size_t shm = GEMM_SMEM_BYTES;
    cudaFuncSetAttribute(gemm_h<0, true >, cudaFuncAttributeMaxDynamicSharedMemorySize, shm);
    cudaFuncSetAttribute(gemm_h<1, true >, cudaFuncAttributeMaxDynamicSharedMemorySize, shm);
    cudaFuncSetAttribute(gemm_h<2, false>, cudaFuncAttributeMaxDynamicSharedMemorySize, shm);
    cudaFuncSetAttribute(gemm_h<3, false>, cudaFuncAttributeMaxDynamicSharedMemorySize, shm);

    detect_mask_kernel<<<1, 256>>>((const unsigned char*)mask);

    // fp32 -> fp16 inputs (q and k in one launch)
    const long long n4 = (long long)MFULL * DD / 4;
    convert2_h_kernel<<<(int)((2 * n4 + 255) / 256), 256>>>(q, qh, k, kh, n4);

    // All 6 weight transposes in one launch
    WtPtrs wp;
    wp.s[0] = qw1; wp.s[1] = qw2; wp.s[2] = qw3;
    wp.s[3] = kw1; wp.s[4] = kw2; wp.s[5] = kw3;
    transpose_w6_kernel<<<dim3(16, 16, 6), dim3(32, 8)>>>(wp, wt);
    __half* wtq1 = wt + 0LL * DD * DD; __half* wtq2 = wt + 1LL * DD * DD;
    __half* wtq3 = wt + 2LL * DD * DD; __half* wtk1 = wt + 3LL * DD * DD;
    __half* wtk2 = wt + 4LL * DD * DD; __half* wtk3 = wt + 5LL * DD * DD;

    // V transpose
    transpose_v_kernel<<<dim3(DD / 32, SS / 32, BB), dim3(32, 8)>>>(v, vt);

    // ---- dual MLP chains (q: z=0, k: z=1) ----
    const dim3 gMLP(DD / 128, MFULL / 128, 2);   // (4, 128, 2)
    gemm_h<0, true><<<gMLP, 256, shm>>>(qh, wtq1, qb1, t1, kh, wtk1, kb1, t3,
                                        DD, DD, 0, 0, 0, nullptr);
    gemm_h<1, true><<<gMLP, 256, shm>>>(t1, wtq2, qb2, t2, t3, wtk2, kb2, t4,
                                        DD, DD, 0, 0, 0, nullptr);
    ln_relu_h2_kernel<<<2 * MFULL, 128>>>(t2, t1, q_ln_g, q_ln_b,
                                          t4, t3, k_ln_g, k_ln_b);
    gemm_h<1, true><<<gMLP, 256, shm>>>(t1, wtq3, qb3, dq, t3, wtk3, kb3, dk,
                                        DD, DD, 0, 0, 0, nullptr);

    // ---- attention ----
    gemm_h<2, false><<<dim3(SS / 128, SS / 128, BB), 256, shm>>>(
        dq, dk, nullptr, ah, nullptr, nullptr, nullptr, nullptr,
        DD, SS, (long long)SS * DD, (long long)SS * DD, (long long)SS * SS, mask);
    softmax_neg_kernel<<<MFULL, 256>>>(ah, attn);
    gemm_h<3, false><<<dim3(DD / 128, SS / 128, BB), 256, shm>>>(
        ah, vt, nullptr, out, nullptr, nullptr, nullptr, nullptr,
        SS, DD, (long long)SS * SS, (long long)DD * SS, (long long)SS * DD, nullptr);
}

// round 13
// speedup vs baseline: 1.1721x; 1.0364x over previous
#include <cuda_runtime.h>
#include <cuda_fp16.h>
#include <math.h>
#include <stdint.h>

// Problem constants
#define BB 8
#define SS 2048
#define DD 512
#define MFULL (BB * SS)          // 16384
#define INV_T (1.0f / 22.627416997969522f)
#define LN_EPS 1e-5f

// GEMM tiling: 128x128 block tile, K-slab 64, 3-stage cp.async, ldmatrix
#define TKS 64
#define NSTAGE 3
#define RS 72                                  // row stride in halves (64 + 8 pad)
#define TILE_HALVES (128 * RS)                 // 9216
#define STAGE_HALVES (2 * TILE_HALVES)         // 18432
#define GEMM_SMEM_BYTES (NSTAGE * STAGE_HALVES * 2)   // 110592

// ---------------------------------------------------------------------------
// Scratch (device globals; no allocations allowed)
// ---------------------------------------------------------------------------
__device__ __half g_qh[MFULL * DD];
__device__ __half g_kh[MFULL * DD];
__device__ __half g_t1[MFULL * DD];
__device__ __half g_t2[MFULL * DD];
__device__ __half g_t3[MFULL * DD];
__device__ __half g_t4[MFULL * DD];
__device__ __half g_dq[MFULL * DD];
__device__ __half g_dk[MFULL * DD];
__device__ __half g_wt[6 * DD * DD];
__device__ __half g_vt[BB * DD * SS];
__device__ __half g_ah[(long long)BB * SS * SS];   // logits, then probs (half)
__device__ int    g_mask_is_i32;

// ---------------------------------------------------------------------------
// helpers
// ---------------------------------------------------------------------------
__device__ __forceinline__ uint32_t smem_u32(const void* p) {
    uint32_t a;
    asm("{ .reg .u64 t; cvta.to.shared.u64 t, %1; cvt.u32.u64 %0, t; }" : "=r"(a) : "l"(p));
    return a;
}

__device__ __forceinline__ void mma_f16(float4& d,
    uint32_t a0, uint32_t a1, uint32_t a2, uint32_t a3,
    uint32_t b0, uint32_t b1)
{
    asm volatile(
        "mma.sync.aligned.m16n8k16.row.col.f32.f16.f16.f32 "
        "{%0,%1,%2,%3}, {%4,%5,%6,%7}, {%8,%9}, {%0,%1,%2,%3};\n"
        : "+f"(d.x), "+f"(d.y), "+f"(d.z), "+f"(d.w)
        : "r"(a0), "r"(a1), "r"(a2), "r"(a3), "r"(b0), "r"(b1));
}

#define LDMATRIX_X4(r0, r1, r2, r3, addr) \
    asm volatile("ldmatrix.sync.aligned.m8n8.x4.shared.b16 {%0,%1,%2,%3}, [%4];" \
        : "=r"(r0), "=r"(r1), "=r"(r2), "=r"(r3) : "r"(addr))

#define CP_ASYNC16(dst_u32, src_ptr) \
    asm volatile("cp.async.cg.shared.global [%0], [%1], 16;" \
        :: "r"(dst_u32), "l"(src_ptr) : "memory")
#define CP_COMMIT() asm volatile("cp.async.commit_group;" ::: "memory")
#define CP_WAIT(n)  asm volatile("cp.async.wait_group %0;" :: "n"(n) : "memory")

// ---------------------------------------------------------------------------
// Mask dtype detector
// ---------------------------------------------------------------------------
__global__ void detect_mask_kernel(const unsigned char* __restrict__ mb) {
    __shared__ int any;
    if (threadIdx.x == 0) any = 0;
    __syncthreads();
    for (int i = threadIdx.x; i < 4096; i += blockDim.x) {
        if ((i & 3) && mb[i]) atomicOr(&any, 1);
    }
    __syncthreads();
    if (threadIdx.x == 0) g_mask_is_i32 = any ? 0 : 1;
}

// ---------------------------------------------------------------------------
// fp32 -> fp16 convert, two tensors in one launch
// ---------------------------------------------------------------------------
__global__ void convert2_h_kernel(const float* __restrict__ S0, __half* __restrict__ D0,
                                  const float* __restrict__ S1, __half* __restrict__ D1,
                                  long long n4) {
    long long idx = (long long)blockIdx.x * blockDim.x + threadIdx.x;
    const float* S; __half* D;
    if (idx < n4) { S = S0; D = D0; }
    else if (idx < 2 * n4) { S = S1; D = D1; idx -= n4; }
    else return;
    const long long i = idx * 4;
    const float4 v = *(const float4*)(S + i);
    *(__half2*)(D + i)     = __floats2half2_rn(v.x, v.y);
    *(__half2*)(D + i + 2) = __floats2half2_rn(v.z, v.w);
}

// ---------------------------------------------------------------------------
// Batched 512x512 weight transpose (6 weights in one launch via z)
// ---------------------------------------------------------------------------
struct WtPtrs { const float* s[6]; };
__global__ void transpose_w6_kernel(WtPtrs ps, __half* __restrict__ Dbase) {
    __shared__ float tile[32][33];
    const float* s = ps.s[blockIdx.z];
    __half* d = Dbase + (long long)blockIdx.z * DD * DD;
    const int x = blockIdx.x * 32 + threadIdx.x;
    const int y0 = blockIdx.y * 32;
    #pragma unroll
    for (int i = threadIdx.y; i < 32; i += 8)
        tile[i][threadIdx.x] = s[(long long)(y0 + i) * DD + x];
    __syncthreads();
    const int xo = blockIdx.y * 32 + threadIdx.x;
    const int yo0 = blockIdx.x * 32;
    #pragma unroll
    for (int i = threadIdx.y; i < 32; i += 8)
        d[(long long)(yo0 + i) * DD + xo] = __float2half_rn(tile[threadIdx.x][i]);
}

// ---------------------------------------------------------------------------
// V transpose: fp32 [b][t][d] -> half [b][d][t]; 64t x 32d tiles, half2 writes
// grid: (16 d-tiles, 32 t-tiles, 8 batches), 256 threads
// ---------------------------------------------------------------------------
__global__ void __launch_bounds__(256) transpose_v_kernel(
    const float* __restrict__ V, __half* __restrict__ VT)
{
    __shared__ float sbuf[32 * 65];
    const int tid = threadIdx.x;
    const int d0 = blockIdx.x * 32;
    const int t0 = blockIdx.y * 64;
    const float* src = V + (long long)blockIdx.z * SS * DD;
    __half* dst = VT + (long long)blockIdx.z * DD * SS;

    // load 64 t-rows x 32 d-cols into sbuf[d][t] (stride 65)
    #pragma unroll
    for (int i = 0; i < 8; i++) {
        const int idx = i * 256 + tid;
        const int r = idx >> 5, c = idx & 31;      // r: t in [0,64), c: d in [0,32)
        sbuf[c * 65 + r] = src[(long long)(t0 + r) * DD + d0 + c];
    }
    __syncthreads();
    // write 32 d-rows of 32 half2 (64 t values) each
    #pragma unroll
    for (int i = 0; i < 4; i++) {
        const int idx = i * 256 + tid;
        const int drow = idx >> 5, tp = idx & 31;
        const float a = sbuf[drow * 65 + 2 * tp];
        const float b = sbuf[drow * 65 + 2 * tp + 1];
        *(__half2*)(dst + (long long)(d0 + drow) * SS + t0 + 2 * tp) =
            __floats2half2_rn(a, b);
    }
}

// ===========================================================================
// Multistage fp16 mma.sync NT GEMM (fp32 accumulate), ldmatrix fragments.
//   C[m,n] = epilogue( sum_k A[m,k] * B[n,k] )
// Block tile 128x128, 256 thr, 8 warps (4m x 2n), warp tile 32x64.
// DUAL: blockIdx.z selects pointer set 0/1. !DUAL: z batches via strides.
// EPI: 0 = +bias+relu (half out), 1 = +bias (half out),
//      2 = QK mask/scale (HALF out), 3 = plain (float out)
// ===========================================================================
template<int EPI, bool DUAL>
__global__ void __launch_bounds__(256, 2) gemm_h(
    const __half* __restrict__ A0, const __half* __restrict__ B0,
    const float* __restrict__ bias0, void* __restrict__ C0,
    const __half* __restrict__ A1, const __half* __restrict__ B1,
    const float* __restrict__ bias1, void* __restrict__ C1,
    int K, int ldc, long long sA, long long sB, long long sC,
    const void* __restrict__ maskp)
{
    extern __shared__ __half smh[];
    const uint32_t sbase = smem_u32(smh);
    const int tid  = threadIdx.x;
    const int warp = tid >> 5;
    const int lane = tid & 31;
    const int wm = (warp >> 1) * 32;
    const int wn = (warp & 1) * 64;
    const int z = blockIdx.z;

    const __half* A; const __half* B; const float* bias; void* Cg;
    if (DUAL && z == 1) { A = A1; B = B1; bias = bias1; Cg = C1; }
    else {
        A = A0 + (long long)z * sA;
        B = B0 + (long long)z * sB;
        bias = bias0; Cg = C0;
    }
    const long long csoff = DUAL ? 0 : (long long)z * sC;

    const int bm = blockIdx.y * 128;
    const int bn = blockIdx.x * 128;

    const int lm_row = (lane & 7) + ((lane >> 3) & 1) * 8;
    const int lm_col = ((lane >> 4) & 1) * 8;
    uint32_t offA[2], offB[4];
    #pragma unroll
    for (int i = 0; i < 2; i++)
        offA[i] = (uint32_t)((wm + i * 16 + lm_row) * RS + lm_col);
    #pragma unroll
    for (int j2 = 0; j2 < 4; j2++)
        offB[j2] = (uint32_t)(TILE_HALVES + (wn + j2 * 16 + lm_row) * RS + lm_col);

    auto load_stage = [&](int t, int buf) {
        const __half* Abase = A + (long long)bm * K + t * TKS;
        const __half* Bbase = B + (long long)bn * K + t * TKS;
        const uint32_t s0 = sbase + (uint32_t)(buf * STAGE_HALVES) * 2u;
        #pragma unroll
        for (int i = 0; i < 4; i++) {
            const int c = tid + i * 256;
            const int m = c >> 3, kc = c & 7;
            CP_ASYNC16(s0 + (uint32_t)(m * RS + kc * 8) * 2u,
                       Abase + (long long)m * K + kc * 8);
            CP_ASYNC16(s0 + (uint32_t)(TILE_HALVES + m * RS + kc * 8) * 2u,
                       Bbase + (long long)m * K + kc * 8);
        }
    };

    float4 acc[2][8];
    #pragma unroll
    for (int i = 0; i < 2; i++)
        #pragma unroll
        for (int j = 0; j < 8; j++) acc[i][j] = make_float4(0.f, 0.f, 0.f, 0.f);

    const int T = K / TKS;

    load_stage(0, 0); CP_COMMIT();
    load_stage(1, 1); CP_COMMIT();

    for (int t = 0; t < T; t++) {
        const int buf = t % NSTAGE;
        CP_WAIT(1);
        __syncthreads();
        if (t + 2 < T) load_stage(t + 2, (t + 2) % NSTAGE);
        CP_COMMIT();

        const uint32_t base = sbase + (uint32_t)(buf * STAGE_HALVES) * 2u;

        #pragma unroll
        for (int ks = 0; ks < 4; ks++) {
            const uint32_t ck2 = (uint32_t)(ks * 16) * 2u;
            uint32_t af[2][4];
            LDMATRIX_X4(af[0][0], af[0][1], af[0][2], af[0][3], base + offA[0] * 2u + ck2);
            LDMATRIX_X4(af[1][0], af[1][1], af[1][2], af[1][3], base + offA[1] * 2u + ck2);
            #pragma unroll
            for (int j2 = 0; j2 < 4; j2++) {
                uint32_t m0, m1, m2, m3;
                LDMATRIX_X4(m0, m1, m2, m3, base + offB[j2] * 2u + ck2);
                const int j = j2 * 2;
                mma_f16(acc[0][j],     af[0][0], af[0][1], af[0][2], af[0][3], m0, m2);
                mma_f16(acc[1][j],     af[1][0], af[1][1], af[1][2], af[1][3], m0, m2);
                mma_f16(acc[0][j + 1], af[0][0], af[0][1], af[0][2], af[0][3], m1, m3);
                mma_f16(acc[1][j + 1], af[1][0], af[1][1], af[1][2], af[1][3], m1, m3);
            }
        }
    }

    // Epilogue
    const int is_i32 = (EPI == 2) ? g_mask_is_i32 : 0;
    #pragma unroll
    for (int i = 0; i < 2; i++) {
        const int r0 = bm + wm + i * 16 + (lane >> 2);
        const int r1 = r0 + 8;
        #pragma unroll
        for (int j = 0; j < 8; j++) {
            const int c = bn + wn + j * 8 + (lane & 3) * 2;
            float2 v0 = make_float2(acc[i][j].x, acc[i][j].y);
            float2 v1 = make_float2(acc[i][j].z, acc[i][j].w);
            if (EPI == 0 || EPI == 1) {
                const float2 b = *(const float2*)(bias + c);
                v0.x += b.x; v0.y += b.y;
                v1.x += b.x; v1.y += b.y;
                if (EPI == 0) {
                    v0.x = fmaxf(v0.x, 0.f); v0.y = fmaxf(v0.y, 0.f);
                    v1.x = fmaxf(v1.x, 0.f); v1.y = fmaxf(v1.y, 0.f);
                }
                __half* C = (__half*)Cg + csoff;
                *(__half2*)(C + (long long)r0 * ldc + c) = __floats2half2_rn(v0.x, v0.y);
                *(__half2*)(C + (long long)r1 * ldc + c) = __floats2half2_rn(v1.x, v1.y);
            } else if (EPI == 2) {
                const long long base2 = (long long)z * SS * SS;
                const long long i00 = base2 + (long long)r0 * SS + c;
                const long long i10 = base2 + (long long)r1 * SS + c;
                bool m00, m01, m10, m11;
                if (is_i32) {
                    const int* mi = (const int*)maskp;
                    m00 = mi[i00] != 0; m01 = mi[i00 + 1] != 0;
                    m10 = mi[i10] != 0; m11 = mi[i10 + 1] != 0;
                } else {
                    const unsigned char* mu = (const unsigned char*)maskp;
                    m00 = mu[i00] != 0; m01 = mu[i00 + 1] != 0;
                    m10 = mu[i10] != 0; m11 = mu[i10 + 1] != 0;
                }
                v0.x = m00 ? -60000.f : v0.x * INV_T;
                v0.y = m01 ? -60000.f : v0.y * INV_T;
                v1.x = m10 ? -60000.f : v1.x * INV_T;
                v1.y = m11 ? -60000.f : v1.y * INV_T;
                __half* C = (__half*)Cg + csoff;
                *(__half2*)(C + (long long)r0 * ldc + c) = __floats2half2_rn(v0.x, v0.y);
                *(__half2*)(C + (long long)r1 * ldc + c) = __floats2half2_rn(v1.x, v1.y);
            } else {
                float* C = (float*)Cg + csoff;
                *(float2*)(C + (long long)r0 * ldc + c) = v0;
                *(float2*)(C + (long long)r1 * ldc + c) = v1;
            }
        }
    }
}

// ---------------------------------------------------------------------------
// Block reductions
// ---------------------------------------------------------------------------
__device__ __forceinline__ float blockReduceSum(float v, float* sh) {
    #pragma unroll
    for (int o = 16; o > 0; o >>= 1) v += __shfl_xor_sync(0xffffffffu, v, o);
    __syncthreads();
    if ((threadIdx.x & 31) == 0) sh[threadIdx.x >> 5] = v;
    __syncthreads();
    if (threadIdx.x < 32) {
        v = (threadIdx.x < (blockDim.x >> 5)) ? sh[threadIdx.x] : 0.0f;
        #pragma unroll
        for (int o = 16; o > 0; o >>= 1) v += __shfl_xor_sync(0xffffffffu, v, o);
        if (threadIdx.x == 0) sh[0] = v;
    }
    __syncthreads();
    return sh[0];
}

__device__ __forceinline__ float blockReduceMax(float v, float* sh) {
    #pragma unroll
    for (int o = 16; o > 0; o >>= 1) v = fmaxf(v, __shfl_xor_sync(0xffffffffu, v, o));
    __syncthreads();
    if ((threadIdx.x & 31) == 0) sh[threadIdx.x >> 5] = v;
    __syncthreads();
    if (threadIdx.x < 32) {
        v = (threadIdx.x < (blockDim.x >> 5)) ? sh[threadIdx.x] : -3.0e38f;
        #pragma unroll
        for (int o = 16; o > 0; o >>= 1) v = fmaxf(v, __shfl_xor_sync(0xffffffffu, v, o));
        if (threadIdx.x == 0) sh[0] = v;
    }
    __syncthreads();
    return sh[0];
}

// ---------------------------------------------------------------------------
// LayerNorm + ReLU, dual chain in one launch (q rows then k rows)
// ---------------------------------------------------------------------------
__global__ void ln_relu_h2_kernel(const __half* __restrict__ X0, __half* __restrict__ Y0,
                                  const float* __restrict__ g0, const float* __restrict__ b0,
                                  const __half* __restrict__ X1, __half* __restrict__ Y1,
                                  const float* __restrict__ g1, const float* __restrict__ b1)
{
    __shared__ float sh[32];
    long long row = blockIdx.x;
    const __half* X; __half* Y; const float* g; const float* beta;
    if (row < MFULL) { X = X0; Y = Y0; g = g0; beta = b0; }
    else { row -= MFULL; X = X1; Y = Y1; g = g1; beta = b1; }
    const __half* x = X + row * DD;
    const int t = threadIdx.x;

    const __half2 h0 = *(const __half2*)(x + t * 4);
    const __half2 h1 = *(const __half2*)(x + t * 4 + 2);
    const float2 f0 = __half22float2(h0);
    const float2 f1 = __half22float2(h1);
    float s  = f0.x + f0.y + f1.x + f1.y;
    float sq = f0.x * f0.x + f0.y * f0.y + f1.x * f1.x + f1.y * f1.y;
    s  = blockReduceSum(s, sh);
    sq = blockReduceSum(sq, sh);
    const float mu  = s * (1.0f / DD);
    const float var = sq * (1.0f / DD) - mu * mu;
    const float r = rsqrtf(var + LN_EPS);

    const float4 gv = *(const float4*)(g + t * 4);
    const float4 bv = *(const float4*)(beta + t * 4);
    float y0 = fmaxf((f0.x - mu) * r * gv.x + bv.x, 0.0f);
    float y1 = fmaxf((f0.y - mu) * r * gv.y + bv.y, 0.0f);
    float y2 = fmaxf((f1.x - mu) * r * gv.z + bv.z, 0.0f);
    float y3 = fmaxf((f1.y - mu) * r * gv.w + bv.w, 0.0f);
    *(__half2*)(Y + row * DD + t * 4)     = __floats2half2_rn(y0, y1);
    *(__half2*)(Y + row * DD + t * 4 + 2) = __floats2half2_rn(y2, y3);
}

// ---------------------------------------------------------------------------
// Negated softmax: reads half logits (uint4), writes fp32 attn + half probs
// ---------------------------------------------------------------------------
__global__ void softmax_neg_kernel(__half* __restrict__ PH, float* __restrict__ P) {
    __shared__ float sh[32];
    __half* ph = PH + (long long)blockIdx.x * SS;
    float* p = P + (long long)blockIdx.x * SS;
    const int t = threadIdx.x;

    const uint4 raw = *(const uint4*)(ph + t * 8);
    const __half2* hp = (const __half2*)&raw;
    const float2 a = __half22float2(hp[0]);
    const float2 b = __half22float2(hp[1]);
    const float2 c = __half22float2(hp[2]);
    const float2 d = __half22float2(hp[3]);
    float x[8] = {a.x, a.y, b.x, b.y, c.x, c.y, d.x, d.y};

    float mx = x[0];
    #pragma unroll
    for (int i = 1; i < 8; i++) mx = fmaxf(mx, x[i]);
    mx = blockReduceMax(mx, sh);

    float e[8], s = 0.f;
    #pragma unroll
    for (int i = 0; i < 8; i++) { e[i] = __expf(x[i] - mx); s += e[i]; }
    s = blockReduceSum(s, sh);
    const float inv = -1.0f / s;

    #pragma unroll
    for (int i = 0; i < 8; i++) e[i] *= inv;
    *(float4*)(p + t * 8)     = make_float4(e[0], e[1], e[2], e[3]);
    *(float4*)(p + t * 8 + 4) = make_float4(e[4], e[5], e[6], e[7]);
    uint4 outh;
    __half2* ohp = (__half2*)&outh;
    ohp[0] = __floats2half2_rn(e[0], e[1]);
    ohp[1] = __floats2half2_rn(e[2], e[3]);
    ohp[2] = __floats2half2_rn(e[4], e[5]);
    ohp[3] = __floats2half2_rn(e[6], e[7]);
    *(uint4*)(ph + t * 8) = outh;
}

// ---------------------------------------------------------------------------
// Launch
// ---------------------------------------------------------------------------
extern "C" void kernel_launch(void* const* d_in, const int* in_sizes, int n_in,
                              void* d_out, int out_size)
{
    const float* q   = (const float*)d_in[0];
    const float* k   = (const float*)d_in[1];
    const float* v   = (const float*)d_in[2];
    const void*  mask = d_in[3];
    const float* qw1 = (const float*)d_in[4];
    const float* qw2 = (const float*)d_in[5];
    const float* qw3 = (const float*)d_in[6];
    const float* kw1 = (const float*)d_in[7];
    const float* kw2 = (const float*)d_in[8];
    const float* kw3 = (const float*)d_in[9];
    const float* qb1 = (const float*)d_in[10];
    const float* qb2 = (const float*)d_in[11];
    const float* qb3 = (const float*)d_in[12];
    const float* kb1 = (const float*)d_in[13];
    const float* kb2 = (const float*)d_in[14];
    const float* kb3 = (const float*)d_in[15];
    const float* q_ln_b = (const float*)d_in[16];
    const float* k_ln_b = (const float*)d_in[17];
    const float* q_ln_g = (const float*)d_in[18];
    const float* k_ln_g = (const float*)d_in[19];

    float* out  = (float*)d_out;                              // [B,S,D]
    float* attn = out + (long long)BB * SS * DD;              // [B,S,S]

    __half *qh, *kh, *t1, *t2, *t3, *t4, *dq, *dk, *wt, *vt, *ah;
    cudaGetSymbolAddress((void**)&qh, g_qh);
    cudaGetSymbolAddress((void**)&kh, g_kh);
    cudaGetSymbolAddress((void**)&t1, g_t1);
    cudaGetSymbolAddress((void**)&t2, g_t2);
    cudaGetSymbolAddress((void**)&t3, g_t3);
    cudaGetSymbolAddress((void**)&t4, g_t4);
    cudaGetSymbolAddress((void**)&dq, g_dq);
    cudaGetSymbolAddress((void**)&dk, g_dk);
    cudaGetSymbolAddress((void**)&wt, g_wt);
    cudaGetSymbolAddress((void**)&vt, g_vt);
    cudaGetSymbolAddress((void**)&ah, g_ah);

    const size_t shm = GEMM_SMEM_BYTES;
    cudaFuncSetAttribute(gemm_h<0, true >, cudaFuncAttributeMaxDynamicSharedMemorySize, shm);
    cudaFuncSetAttribute(gemm_h<1, true >, cudaFuncAttributeMaxDynamicSharedMemorySize, shm);
    cudaFuncSetAttribute(gemm_h<2, false>, cudaFuncAttributeMaxDynamicSharedMemorySize, shm);
    cudaFuncSetAttribute(gemm_h<3, false>, cudaFuncAttributeMaxDynamicSharedMemorySize, shm);

    detect_mask_kernel<<<1, 256>>>((const unsigned char*)mask);

    // fp32 -> fp16 inputs (q and k in one launch)
    const long long n4 = (long long)MFULL * DD / 4;
    convert2_h_kernel<<<(int)((2 * n4 + 255) / 256), 256>>>(q, qh, k, kh, n4);

    // All 6 weight transposes in one launch
    WtPtrs wp;
    wp.s[0] = qw1; wp.s[1] = qw2; wp.s[2] = qw3;
    wp.s[3] = kw1; wp.s[4] = kw2; wp.s[5] = kw3;
    transpose_w6_kernel<<<dim3(16, 16, 6), dim3(32, 8)>>>(wp, wt);
    __half* wtq1 = wt + 0LL * DD * DD; __half* wtq2 = wt + 1LL * DD * DD;
    __half* wtq3 = wt + 2LL * DD * DD; __half* wtk1 = wt + 3LL * DD * DD;
    __half* wtk2 = wt + 4LL * DD * DD; __half* wtk3 = wt + 5LL * DD * DD;

    // V transpose (half2-packed writes)
    transpose_v_kernel<<<dim3(DD / 32, SS / 64, BB), 256>>>(v, vt);

    // ---- dual MLP chains (q: z=0, k: z=1) ----
    const dim3 gMLP(DD / 128, MFULL / 128, 2);   // (4, 128, 2)
    gemm_h<0, true><<<gMLP, 256, shm>>>(qh, wtq1, qb1, t1, kh, wtk1, kb1, t3,
                                        DD, DD, 0, 0, 0, nullptr);
    gemm_h<1, true><<<gMLP, 256, shm>>>(t1, wtq2, qb2, t2, t3, wtk2, kb2, t4,
                                        DD, DD, 0, 0, 0, nullptr);
    ln_relu_h2_kernel<<<2 * MFULL, 128>>>(t2, t1, q_ln_g, q_ln_b,
                                          t4, t3, k_ln_g, k_ln_b);
    gemm_h<1, true><<<gMLP, 256, shm>>>(t1, wtq3, qb3, dq, t3, wtk3, kb3, dk,
                                        DD, DD, 0, 0, 0, nullptr);

    // ---- attention ----
    gemm_h<2, false><<<dim3(SS / 128, SS / 128, BB), 256, shm>>>(
        dq, dk, nullptr, ah, nullptr, nullptr, nullptr, nullptr,
        DD, SS, (long long)SS * DD, (long long)SS * DD, (long long)SS * SS, mask);
    softmax_neg_kernel<<<MFULL, 256>>>(ah, attn);
    gemm_h<3, false><<<dim3(DD / 128, SS / 128, BB), 256, shm>>>(
        ah, vt, nullptr, out, nullptr, nullptr, nullptr, nullptr,
        SS, DD, (long long)SS * SS, (long long)DD * SS, (long long)SS * DD, nullptr);
}

// round 15
// speedup vs baseline: 1.2198x; 1.0407x over previous
#include <cuda_runtime.h>
#include <cuda_fp16.h>
#include <math.h>
#include <stdint.h>

// Problem constants
#define BB 8
#define SS 2048
#define DD 512
#define MFULL (BB * SS)          // 16384
#define INV_T (1.0f / 22.627416997969522f)
#define LN_EPS 1e-5f

// GEMM tiling: 128x128 block tile, K-slab 64, 3-stage cp.async, ldmatrix
#define TKS 64
#define NSTAGE 3
#define RS 72                                  // row stride in halves (64 + 8 pad)
#define TILE_HALVES (128 * RS)                 // 9216
#define STAGE_HALVES (2 * TILE_HALVES)         // 18432
#define GEMM_SMEM_BYTES (NSTAGE * STAGE_HALVES * 2)   // 110592
#define CS 136                                 // epilogue staging row stride (halves)

// ---------------------------------------------------------------------------
// Scratch (device globals; no allocations allowed)
// ---------------------------------------------------------------------------
__device__ __half g_qh[MFULL * DD];
__device__ __half g_kh[MFULL * DD];
__device__ __half g_t1[MFULL * DD];
__device__ __half g_t2[MFULL * DD];
__device__ __half g_t3[MFULL * DD];
__device__ __half g_t4[MFULL * DD];
__device__ __half g_dq[MFULL * DD];
__device__ __half g_dk[MFULL * DD];
__device__ __half g_wt[6 * DD * DD];
__device__ __half g_vt[BB * DD * SS];
__device__ __half g_ah[(long long)BB * SS * SS];   // logits, then probs (half)
__device__ int    g_mask_is_i32;

// ---------------------------------------------------------------------------
// helpers
// ---------------------------------------------------------------------------
__device__ __forceinline__ uint32_t smem_u32(const void* p) {
    uint32_t a;
    asm("{ .reg .u64 t; cvta.to.shared.u64 t, %1; cvt.u32.u64 %0, t; }" : "=r"(a) : "l"(p));
    return a;
}

__device__ __forceinline__ void mma_f16(float4& d,
    uint32_t a0, uint32_t a1, uint32_t a2, uint32_t a3,
    uint32_t b0, uint32_t b1)
{
    asm volatile(
        "mma.sync.aligned.m16n8k16.row.col.f32.f16.f16.f32 "
        "{%0,%1,%2,%3}, {%4,%5,%6,%7}, {%8,%9}, {%0,%1,%2,%3};\n"
        : "+f"(d.x), "+f"(d.y), "+f"(d.z), "+f"(d.w)
        : "r"(a0), "r"(a1), "r"(a2), "r"(a3), "r"(b0), "r"(b1));
}

#define LDMATRIX_X4(r0, r1, r2, r3, addr) \
    asm volatile("ldmatrix.sync.aligned.m8n8.x4.shared.b16 {%0,%1,%2,%3}, [%4];" \
        : "=r"(r0), "=r"(r1), "=r"(r2), "=r"(r3) : "r"(addr))

#define CP_ASYNC16(dst_u32, src_ptr) \
    asm volatile("cp.async.cg.shared.global [%0], [%1], 16;" \
        :: "r"(dst_u32), "l"(src_ptr) : "memory")
#define CP_COMMIT() asm volatile("cp.async.commit_group;" ::: "memory")
#define CP_WAIT(n)  asm volatile("cp.async.wait_group %0;" :: "n"(n) : "memory")

// ---------------------------------------------------------------------------
// Mask dtype detector
// ---------------------------------------------------------------------------
__global__ void detect_mask_kernel(const unsigned char* __restrict__ mb) {
    __shared__ int any;
    if (threadIdx.x == 0) any = 0;
    __syncthreads();
    for (int i = threadIdx.x; i < 4096; i += blockDim.x) {
        if ((i & 3) && mb[i]) atomicOr(&any, 1);
    }
    __syncthreads();
    if (threadIdx.x == 0) g_mask_is_i32 = any ? 0 : 1;
}

// ---------------------------------------------------------------------------
// fp32 -> fp16 convert, two tensors in one launch
// ---------------------------------------------------------------------------
__global__ void convert2_h_kernel(const float* __restrict__ S0, __half* __restrict__ D0,
                                  const float* __restrict__ S1, __half* __restrict__ D1,
                                  long long n4) {
    long long idx = (long long)blockIdx.x * blockDim.x + threadIdx.x;
    const float* S; __half* D;
    if (idx < n4) { S = S0; D = D0; }
    else if (idx < 2 * n4) { S = S1; D = D1; idx -= n4; }
    else return;
    const long long i = idx * 4;
    const float4 v = *(const float4*)(S + i);
    *(__half2*)(D + i)     = __floats2half2_rn(v.x, v.y);
    *(__half2*)(D + i + 2) = __floats2half2_rn(v.z, v.w);
}

// ---------------------------------------------------------------------------
// Batched 512x512 weight transpose (6 weights in one launch via z)
// ---------------------------------------------------------------------------
struct WtPtrs { const float* s[6]; };
__global__ void transpose_w6_kernel(WtPtrs ps, __half* __restrict__ Dbase) {
    __shared__ float tile[32][33];
    const float* s = ps.s[blockIdx.z];
    __half* d = Dbase + (long long)blockIdx.z * DD * DD;
    const int x = blockIdx.x * 32 + threadIdx.x;
    const int y0 = blockIdx.y * 32;
    #pragma unroll
    for (int i = threadIdx.y; i < 32; i += 8)
        tile[i][threadIdx.x] = s[(long long)(y0 + i) * DD + x];
    __syncthreads();
    const int xo = blockIdx.y * 32 + threadIdx.x;
    const int yo0 = blockIdx.x * 32;
    #pragma unroll
    for (int i = threadIdx.y; i < 32; i += 8)
        d[(long long)(yo0 + i) * DD + xo] = __float2half_rn(tile[threadIdx.x][i]);
}

// ---------------------------------------------------------------------------
// V transpose: fp32 [b][t][d] -> half [b][d][t]; 64t x 32d tiles, half2 writes
// ---------------------------------------------------------------------------
__global__ void __launch_bounds__(256) transpose_v_kernel(
    const float* __restrict__ V, __half* __restrict__ VT)
{
    __shared__ float sbuf[32 * 65];
    const int tid = threadIdx.x;
    const int d0 = blockIdx.x * 32;
    const int t0 = blockIdx.y * 64;
    const float* src = V + (long long)blockIdx.z * SS * DD;
    __half* dst = VT + (long long)blockIdx.z * DD * SS;

    #pragma unroll
    for (int i = 0; i < 8; i++) {
        const int idx = i * 256 + tid;
        const int r = idx >> 5, c = idx & 31;
        sbuf[c * 65 + r] = src[(long long)(t0 + r) * DD + d0 + c];
    }
    __syncthreads();
    #pragma unroll
    for (int i = 0; i < 4; i++) {
        const int idx = i * 256 + tid;
        const int drow = idx >> 5, tp = idx & 31;
        const float a = sbuf[drow * 65 + 2 * tp];
        const float b = sbuf[drow * 65 + 2 * tp + 1];
        *(__half2*)(dst + (long long)(d0 + drow) * SS + t0 + 2 * tp) =
            __floats2half2_rn(a, b);
    }
}

// ===========================================================================
// Multistage fp16 mma.sync NT GEMM (fp32 accumulate), ldmatrix fragments.
//   C[m,n] = epilogue( sum_k A[m,k] * B[n,k] )
// Block tile 128x128, 256 thr, 8 warps (4m x 2n), warp tile 32x64.
// DUAL: blockIdx.z selects pointer set 0/1. !DUAL: z batches via strides.
// EPI: 0 = +bias+relu (half out), 1 = +bias (half out),
//      2 = QK mask/scale (HALF out), 3 = plain (float out)
// Half outputs (EPI 0/1/2) are staged through smem for coalesced 16B stores.
// ===========================================================================
template<int EPI, bool DUAL>
__global__ void __launch_bounds__(256, 2) gemm_h(
    const __half* __restrict__ A0, const __half* __restrict__ B0,
    const float* __restrict__ bias0, void* __restrict__ C0,
    const __half* __restrict__ A1, const __half* __restrict__ B1,
    const float* __restrict__ bias1, void* __restrict__ C1,
    int K, int ldc, long long sA, long long sB, long long sC,
    const void* __restrict__ maskp)
{
    extern __shared__ __half smh[];
    const uint32_t sbase = smem_u32(smh);
    const int tid  = threadIdx.x;
    const int warp = tid >> 5;
    const int lane = tid & 31;
    const int wm = (warp >> 1) * 32;
    const int wn = (warp & 1) * 64;
    const int z = blockIdx.z;

    const __half* A; const __half* B; const float* bias; void* Cg;
    if (DUAL && z == 1) { A = A1; B = B1; bias = bias1; Cg = C1; }
    else {
        A = A0 + (long long)z * sA;
        B = B0 + (long long)z * sB;
        bias = bias0; Cg = C0;
    }
    const long long csoff = DUAL ? 0 : (long long)z * sC;

    const int bm = blockIdx.y * 128;
    const int bn = blockIdx.x * 128;

    const int lm_row = (lane & 7) + ((lane >> 3) & 1) * 8;
    const int lm_col = ((lane >> 4) & 1) * 8;
    uint32_t offA[2], offB[4];
    #pragma unroll
    for (int i = 0; i < 2; i++)
        offA[i] = (uint32_t)((wm + i * 16 + lm_row) * RS + lm_col);
    #pragma unroll
    for (int j2 = 0; j2 < 4; j2++)
        offB[j2] = (uint32_t)(TILE_HALVES + (wn + j2 * 16 + lm_row) * RS + lm_col);

    auto load_stage = [&](int t, int buf) {
        const __half* Abase = A + (long long)bm * K + t * TKS;
        const __half* Bbase = B + (long long)bn * K + t * TKS;
        const uint32_t s0 = sbase + (uint32_t)(buf * STAGE_HALVES) * 2u;
        #pragma unroll
        for (int i = 0; i < 4; i++) {
            const int c = tid + i * 256;
            const int m = c >> 3, kc = c & 7;
            CP_ASYNC16(s0 + (uint32_t)(m * RS + kc * 8) * 2u,
                       Abase + (long long)m * K + kc * 8);
            CP_ASYNC16(s0 + (uint32_t)(TILE_HALVES + m * RS + kc * 8) * 2u,
                       Bbase + (long long)m * K + kc * 8);
        }
    };

    float4 acc[2][8];
    #pragma unroll
    for (int i = 0; i < 2; i++)
        #pragma unroll
        for (int j = 0; j < 8; j++) acc[i][j] = make_float4(0.f, 0.f, 0.f, 0.f);

    const int T = K / TKS;

    load_stage(0, 0); CP_COMMIT();
    load_stage(1, 1); CP_COMMIT();

    for (int t = 0; t < T; t++) {
        const int buf = t % NSTAGE;
        CP_WAIT(1);
        __syncthreads();
        if (t + 2 < T) load_stage(t + 2, (t + 2) % NSTAGE);
        CP_COMMIT();

        const uint32_t base = sbase + (uint32_t)(buf * STAGE_HALVES) * 2u;

        #pragma unroll
        for (int ks = 0; ks < 4; ks++) {
            const uint32_t ck2 = (uint32_t)(ks * 16) * 2u;
            uint32_t af[2][4];
            LDMATRIX_X4(af[0][0], af[0][1], af[0][2], af[0][3], base + offA[0] * 2u + ck2);
            LDMATRIX_X4(af[1][0], af[1][1], af[1][2], af[1][3], base + offA[1] * 2u + ck2);
            #pragma unroll
            for (int j2 = 0; j2 < 4; j2++) {
                uint32_t m0, m1, m2, m3;
                LDMATRIX_X4(m0, m1, m2, m3, base + offB[j2] * 2u + ck2);
                const int j = j2 * 2;
                mma_f16(acc[0][j],     af[0][0], af[0][1], af[0][2], af[0][3], m0, m2);
                mma_f16(acc[1][j],     af[1][0], af[1][1], af[1][2], af[1][3], m0, m2);
                mma_f16(acc[0][j + 1], af[0][0], af[0][1], af[0][2], af[0][3], m1, m3);
                mma_f16(acc[1][j + 1], af[1][0], af[1][1], af[1][2], af[1][3], m1, m3);
            }
        }
    }

    // -------------------- Epilogue --------------------
    if (EPI == 3) {
        // fp32 output: direct stores (full 32B sectors)
        #pragma unroll
        for (int i = 0; i < 2; i++) {
            const int r0 = bm + wm + i * 16 + (lane >> 2);
            const int r1 = r0 + 8;
            #pragma unroll
            for (int j = 0; j < 8; j++) {
                const int c = bn + wn + j * 8 + (lane & 3) * 2;
                float* C = (float*)Cg + csoff;
                *(float2*)(C + (long long)r0 * ldc + c) = make_float2(acc[i][j].x, acc[i][j].y);
                *(float2*)(C + (long long)r1 * ldc + c) = make_float2(acc[i][j].z, acc[i][j].w);
            }
        }
    } else {
        // half output: stage tile in smem, then coalesced 16B row stores
        const int is_i32 = (EPI == 2) ? g_mask_is_i32 : 0;
        __syncthreads();                       // all smem reads done; reuse as staging
        #pragma unroll
        for (int i = 0; i < 2; i++) {
            const int rl0 = wm + i * 16 + (lane >> 2);
            const int rl1 = rl0 + 8;
            #pragma unroll
            for (int j = 0; j < 8; j++) {
                const int cl = wn + j * 8 + (lane & 3) * 2;
                float2 v0 = make_float2(acc[i][j].x, acc[i][j].y);
                float2 v1 = make_float2(acc[i][j].z, acc[i][j].w);
                if (EPI == 0 || EPI == 1) {
                    const float2 b = *(const float2*)(bias + bn + cl);
                    v0.x += b.x; v0.y += b.y;
                    v1.x += b.x; v1.y += b.y;
                    if (EPI == 0) {
                        v0.x = fmaxf(v0.x, 0.f); v0.y = fmaxf(v0.y, 0.f);
                        v1.x = fmaxf(v1.x, 0.f); v1.y = fmaxf(v1.y, 0.f);
                    }
                } else {   // EPI == 2
                    const long long base2 = (long long)z * SS * SS;
                    const long long i00 = base2 + (long long)(bm + rl0) * SS + bn + cl;
                    const long long i10 = base2 + (long long)(bm + rl1) * SS + bn + cl;
                    bool m00, m01, m10, m11;
                    if (is_i32) {
                        const int* mi = (const int*)maskp;
                        m00 = mi[i00] != 0; m01 = mi[i00 + 1] != 0;
                        m10 = mi[i10] != 0; m11 = mi[i10 + 1] != 0;
                    } else {
                        const unsigned char* mu = (const unsigned char*)maskp;
                        m00 = mu[i00] != 0; m01 = mu[i00 + 1] != 0;
                        m10 = mu[i10] != 0; m11 = mu[i10 + 1] != 0;
                    }
                    v0.x = m00 ? -60000.f : v0.x * INV_T;
                    v0.y = m01 ? -60000.f : v0.y * INV_T;
                    v1.x = m10 ? -60000.f : v1.x * INV_T;
                    v1.y = m11 ? -60000.f : v1.y * INV_T;
                }
                *(__half2*)(smh + rl0 * CS + cl) = __floats2half2_rn(v0.x, v0.y);
                *(__half2*)(smh + rl1 * CS + cl) = __floats2half2_rn(v1.x, v1.y);
            }
        }
        __syncthreads();
        __half* C = (__half*)Cg + csoff;
        #pragma unroll
        for (int p = 0; p < 8; p++) {
            const int r = p * 16 + (tid >> 4);
            const int ch = (tid & 15) * 8;
            *(uint4*)(C + (long long)(bm + r) * ldc + bn + ch) =
                *(const uint4*)(smh + r * CS + ch);
        }
    }
}

// ---------------------------------------------------------------------------
// Block reduction (sum)
// ---------------------------------------------------------------------------
__device__ __forceinline__ float blockReduceSum(float v, float* sh) {
    #pragma unroll
    for (int o = 16; o > 0; o >>= 1) v += __shfl_xor_sync(0xffffffffu, v, o);
    __syncthreads();
    if ((threadIdx.x & 31) == 0) sh[threadIdx.x >> 5] = v;
    __syncthreads();
    if (threadIdx.x < 32) {
        v = (threadIdx.x < (blockDim.x >> 5)) ? sh[threadIdx.x] : 0.0f;
        #pragma unroll
        for (int o = 16; o > 0; o >>= 1) v += __shfl_xor_sync(0xffffffffu, v, o);
        if (threadIdx.x == 0) sh[0] = v;
    }
    __syncthreads();
    return sh[0];
}

// ---------------------------------------------------------------------------
// LayerNorm + ReLU, dual chain in one launch (q rows then k rows)
// ---------------------------------------------------------------------------
__global__ void ln_relu_h2_kernel(const __half* __restrict__ X0, __half* __restrict__ Y0,
                                  const float* __restrict__ g0, const float* __restrict__ b0,
                                  const __half* __restrict__ X1, __half* __restrict__ Y1,
                                  const float* __restrict__ g1, const float* __restrict__ b1)
{
    __shared__ float sh[32];
    long long row = blockIdx.x;
    const __half* X; __half* Y; const float* g; const float* beta;
    if (row < MFULL) { X = X0; Y = Y0; g = g0; beta = b0; }
    else { row -= MFULL; X = X1; Y = Y1; g = g1; beta = b1; }
    const __half* x = X + row * DD;
    const int t = threadIdx.x;

    const __half2 h0 = *(const __half2*)(x + t * 4);
    const __half2 h1 = *(const __half2*)(x + t * 4 + 2);
    const float2 f0 = __half22float2(h0);
    const float2 f1 = __half22float2(h1);
    float s  = f0.x + f0.y + f1.x + f1.y;
    float sq = f0.x * f0.x + f0.y * f0.y + f1.x * f1.x + f1.y * f1.y;
    s  = blockReduceSum(s, sh);
    sq = blockReduceSum(sq, sh);
    const float mu  = s * (1.0f / DD);
    const float var = sq * (1.0f / DD) - mu * mu;
    const float r = rsqrtf(var + LN_EPS);

    const float4 gv = *(const float4*)(g + t * 4);
    const float4 bv = *(const float4*)(beta + t * 4);
    float y0 = fmaxf((f0.x - mu) * r * gv.x + bv.x, 0.0f);
    float y1 = fmaxf((f0.y - mu) * r * gv.y + bv.y, 0.0f);
    float y2 = fmaxf((f1.x - mu) * r * gv.z + bv.z, 0.0f);
    float y3 = fmaxf((f1.y - mu) * r * gv.w + bv.w, 0.0f);
    *(__half2*)(Y + row * DD + t * 4)     = __floats2half2_rn(y0, y1);
    *(__half2*)(Y + row * DD + t * 4 + 2) = __floats2half2_rn(y2, y3);
}

// ---------------------------------------------------------------------------
// Negated softmax (no max pass — logits bounded, masked = -60000 -> exp = 0):
// reads half logits (uint4), writes fp32 attn + half probs
// ---------------------------------------------------------------------------
__global__ void softmax_neg_kernel(__half* __restrict__ PH, float* __restrict__ P) {
    __shared__ float sh[32];
    __half* ph = PH + (long long)blockIdx.x * SS;
    float* p = P + (long long)blockIdx.x * SS;
    const int t = threadIdx.x;

    const uint4 raw = *(const uint4*)(ph + t * 8);
    const __half2* hp = (const __half2*)&raw;
    const float2 a = __half22float2(hp[0]);
    const float2 b = __half22float2(hp[1]);
    const float2 c = __half22float2(hp[2]);
    const float2 d = __half22float2(hp[3]);
    float x[8] = {a.x, a.y, b.x, b.y, c.x, c.y, d.x, d.y};

    float e[8], s = 0.f;
    #pragma unroll
    for (int i = 0; i < 8; i++) { e[i] = __expf(x[i]); s += e[i]; }
    s = blockReduceSum(s, sh);
    const float inv = -1.0f / s;

    #pragma unroll
    for (int i = 0; i < 8; i++) e[i] *= inv;
    *(float4*)(p + t * 8)     = make_float4(e[0], e[1], e[2], e[3]);
    *(float4*)(p + t * 8 + 4) = make_float4(e[4], e[5], e[6], e[7]);
    uint4 outh;
    __half2* ohp = (__half2*)&outh;
    ohp[0] = __floats2half2_rn(e[0], e[1]);
    ohp[1] = __floats2half2_rn(e[2], e[3]);
    ohp[2] = __floats2half2_rn(e[4], e[5]);
    ohp[3] = __floats2half2_rn(e[6], e[7]);
    *(uint4*)(ph + t * 8) = outh;
}

// ---------------------------------------------------------------------------
// Launch
// ---------------------------------------------------------------------------
extern "C" void kernel_launch(void* const* d_in, const int* in_sizes, int n_in,
                              void* d_out, int out_size)
{
    const float* q   = (const float*)d_in[0];
    const float* k   = (const float*)d_in[1];
    const float* v   = (const float*)d_in[2];
    const void*  mask = d_in[3];
    const float* qw1 = (const float*)d_in[4];
    const float* qw2 = (const float*)d_in[5];
    const float* qw3 = (const float*)d_in[6];
    const float* kw1 = (const float*)d_in[7];
    const float* kw2 = (const float*)d_in[8];
    const float* kw3 = (const float*)d_in[9];
    const float* qb1 = (const float*)d_in[10];
    const float* qb2 = (const float*)d_in[11];
    const float* qb3 = (const float*)d_in[12];
    const float* kb1 = (const float*)d_in[13];
    const float* kb2 = (const float*)d_in[14];
    const float* kb3 = (const float*)d_in[15];
    const float* q_ln_b = (const float*)d_in[16];
    const float* k_ln_b = (const float*)d_in[17];
    const float* q_ln_g = (const float*)d_in[18];
    const float* k_ln_g = (const float*)d_in[19];

    float* out  = (float*)d_out;                              // [B,S,D]
    float* attn = out + (long long)BB * SS * DD;              // [B,S,S]

    __half *qh, *kh, *t1, *t2, *t3, *t4, *dq, *dk, *wt, *vt, *ah;
    cudaGetSymbolAddress((void**)&qh, g_qh);
    cudaGetSymbolAddress((void**)&kh, g_kh);
    cudaGetSymbolAddress((void**)&t1, g_t1);
    cudaGetSymbolAddress((void**)&t2, g_t2);
    cudaGetSymbolAddress((void**)&t3, g_t3);
    cudaGetSymbolAddress((void**)&t4, g_t4);
    cudaGetSymbolAddress((void**)&dq, g_dq);
    cudaGetSymbolAddress((void**)&dk, g_dk);
    cudaGetSymbolAddress((void**)&wt, g_wt);
    cudaGetSymbolAddress((void**)&vt, g_vt);
    cudaGetSymbolAddress((void**)&ah, g_ah);

    const size_t shm = GEMM_SMEM_BYTES;
    cudaFuncSetAttribute(gemm_h<0, true >, cudaFuncAttributeMaxDynamicSharedMemorySize, shm);
    cudaFuncSetAttribute(gemm_h<1, true >, cudaFuncAttributeMaxDynamicSharedMemorySize, shm);
    cudaFuncSetAttribute(gemm_h<2, false>, cudaFuncAttributeMaxDynamicSharedMemorySize, shm);
    cudaFuncSetAttribute(gemm_h<3, false>, cudaFuncAttributeMaxDynamicSharedMemorySize, shm);

    detect_mask_kernel<<<1, 256>>>((const unsigned char*)mask);

    // fp32 -> fp16 inputs (q and k in one launch)
    const long long n4 = (long long)MFULL * DD / 4;
    convert2_h_kernel<<<(int)((2 * n4 + 255) / 256), 256>>>(q, qh, k, kh, n4);

    // All 6 weight transposes in one launch
    WtPtrs wp;
    wp.s[0] = qw1; wp.s[1] = qw2; wp.s[2] = qw3;
    wp.s[3] = kw1; wp.s[4] = kw2; wp.s[5] = kw3;
    transpose_w6_kernel<<<dim3(16, 16, 6), dim3(32, 8)>>>(wp, wt);
    __half* wtq1 = wt + 0LL * DD * DD; __half* wtq2 = wt + 1LL * DD * DD;
    __half* wtq3 = wt + 2LL * DD * DD; __half* wtk1 = wt + 3LL * DD * DD;
    __half* wtk2 = wt + 4LL * DD * DD; __half* wtk3 = wt + 5LL * DD * DD;

    // V transpose (half2-packed writes)
    transpose_v_kernel<<<dim3(DD / 32, SS / 64, BB), 256>>>(v, vt);

    // ---- dual MLP chains (q: z=0, k: z=1) ----
    const dim3 gMLP(DD / 128, MFULL / 128, 2);   // (4, 128, 2)
    gemm_h<0, true><<<gMLP, 256, shm>>>(qh, wtq1, qb1, t1, kh, wtk1, kb1, t3,
                                        DD, DD, 0, 0, 0, nullptr);
    gemm_h<1, true><<<gMLP, 256, shm>>>(t1, wtq2, qb2, t2, t3, wtk2, kb2, t4,
                                        DD, DD, 0, 0, 0, nullptr);
    ln_relu_h2_kernel<<<2 * MFULL, 128>>>(t2, t1, q_ln_g, q_ln_b,
                                          t4, t3, k_ln_g, k_ln_b);
    gemm_h<1, true><<<gMLP, 256, shm>>>(t1, wtq3, qb3, dq, t3, wtk3, kb3, dk,
                                        DD, DD, 0, 0, 0, nullptr);

    // ---- attention ----
    gemm_h<2, false><<<dim3(SS / 128, SS / 128, BB), 256, shm>>>(
        dq, dk, nullptr, ah, nullptr, nullptr, nullptr, nullptr,
        DD, SS, (long long)SS * DD, (long long)SS * DD, (long long)SS * SS, mask);
    softmax_neg_kernel<<<MFULL, 256>>>(ah, attn);
    gemm_h<3, false><<<dim3(DD / 128, SS / 128, BB), 256, shm>>>(
        ah, vt, nullptr, out, nullptr, nullptr, nullptr, nullptr,
        SS, DD, (long long)SS * SS, (long long)DD * SS, (long long)SS * DD, nullptr);
}

// round 16
// speedup vs baseline: 1.2261x; 1.0052x over previous
#include <cuda_runtime.h>
#include <cuda_fp16.h>
#include <math.h>
#include <stdint.h>

// Problem constants
#define BB 8
#define SS 2048
#define DD 512
#define MFULL (BB * SS)          // 16384
#define INV_T (1.0f / 22.627416997969522f)
#define LN_EPS 1e-5f

// GEMM tiling: 128x128 block tile, K-slab 64, 3-stage cp.async, ldmatrix
#define TKS 64
#define NSTAGE 3
#define RS 72                                  // row stride in halves (64 + 8 pad)
#define TILE_HALVES (128 * RS)                 // 9216
#define STAGE_HALVES (2 * TILE_HALVES)         // 18432
#define GEMM_SMEM_BYTES (NSTAGE * STAGE_HALVES * 2)   // 110592
#define CS 136                                 // epilogue staging row stride (halves)

// ---------------------------------------------------------------------------
// Scratch (device globals; no allocations allowed)
// ---------------------------------------------------------------------------
__device__ __half g_qh[MFULL * DD];
__device__ __half g_kh[MFULL * DD];
__device__ __half g_t1[MFULL * DD];
__device__ __half g_t2[MFULL * DD];
__device__ __half g_t3[MFULL * DD];
__device__ __half g_t4[MFULL * DD];
__device__ __half g_dq[MFULL * DD];
__device__ __half g_dk[MFULL * DD];
__device__ __half g_wt[6 * DD * DD];
__device__ __half g_vt[BB * DD * SS];
__device__ __half g_ah[(long long)BB * SS * SS];   // logits, then probs (half)
__device__ int    g_mask_is_i32;

// ---------------------------------------------------------------------------
// helpers
// ---------------------------------------------------------------------------
__device__ __forceinline__ uint32_t smem_u32(const void* p) {
    uint32_t a;
    asm("{ .reg .u64 t; cvta.to.shared.u64 t, %1; cvt.u32.u64 %0, t; }" : "=r"(a) : "l"(p));
    return a;
}

__device__ __forceinline__ void mma_f16(float4& d,
    uint32_t a0, uint32_t a1, uint32_t a2, uint32_t a3,
    uint32_t b0, uint32_t b1)
{
    asm volatile(
        "mma.sync.aligned.m16n8k16.row.col.f32.f16.f16.f32 "
        "{%0,%1,%2,%3}, {%4,%5,%6,%7}, {%8,%9}, {%0,%1,%2,%3};\n"
        : "+f"(d.x), "+f"(d.y), "+f"(d.z), "+f"(d.w)
        : "r"(a0), "r"(a1), "r"(a2), "r"(a3), "r"(b0), "r"(b1));
}

#define LDMATRIX_X4(r0, r1, r2, r3, addr) \
    asm volatile("ldmatrix.sync.aligned.m8n8.x4.shared.b16 {%0,%1,%2,%3}, [%4];" \
        : "=r"(r0), "=r"(r1), "=r"(r2), "=r"(r3) : "r"(addr))

#define CP_ASYNC16(dst_u32, src_ptr) \
    asm volatile("cp.async.cg.shared.global [%0], [%1], 16;" \
        :: "r"(dst_u32), "l"(src_ptr) : "memory")
#define CP_COMMIT() asm volatile("cp.async.commit_group;" ::: "memory")
#define CP_WAIT(n)  asm volatile("cp.async.wait_group %0;" :: "n"(n) : "memory")

// streaming fp32x2 store (evict-first; output never re-read)
__device__ __forceinline__ void stwt_f2(float* p, float2 v) {
    asm volatile("st.global.wt.v2.f32 [%0], {%1, %2};" :: "l"(p), "f"(v.x), "f"(v.y) : "memory");
}
__device__ __forceinline__ void stwt_f4(float* p, float4 v) {
    asm volatile("st.global.wt.v4.f32 [%0], {%1, %2, %3, %4};"
                 :: "l"(p), "f"(v.x), "f"(v.y), "f"(v.z), "f"(v.w) : "memory");
}

// ---------------------------------------------------------------------------
// Mask dtype detector
// ---------------------------------------------------------------------------
__global__ void detect_mask_kernel(const unsigned char* __restrict__ mb) {
    __shared__ int any;
    if (threadIdx.x == 0) any = 0;
    __syncthreads();
    for (int i = threadIdx.x; i < 4096; i += blockDim.x) {
        if ((i & 3) && mb[i]) atomicOr(&any, 1);
    }
    __syncthreads();
    if (threadIdx.x == 0) g_mask_is_i32 = any ? 0 : 1;
}

// ---------------------------------------------------------------------------
// fp32 -> fp16 convert, two tensors in one launch; 8 elems/thread, 16B stores
// ---------------------------------------------------------------------------
__global__ void convert2_h_kernel(const float* __restrict__ S0, __half* __restrict__ D0,
                                  const float* __restrict__ S1, __half* __restrict__ D1,
                                  long long n8) {
    long long idx = (long long)blockIdx.x * blockDim.x + threadIdx.x;
    const float* S; __half* D;
    if (idx < n8) { S = S0; D = D0; }
    else if (idx < 2 * n8) { S = S1; D = D1; idx -= n8; }
    else return;
    const long long i = idx * 8;
    const float4 v0 = *(const float4*)(S + i);
    const float4 v1 = *(const float4*)(S + i + 4);
    uint4 o;
    __half2* op = (__half2*)&o;
    op[0] = __floats2half2_rn(v0.x, v0.y);
    op[1] = __floats2half2_rn(v0.z, v0.w);
    op[2] = __floats2half2_rn(v1.x, v1.y);
    op[3] = __floats2half2_rn(v1.z, v1.w);
    *(uint4*)(D + i) = o;
}

// ---------------------------------------------------------------------------
// Batched 512x512 weight transpose (6 weights in one launch via z)
// ---------------------------------------------------------------------------
struct WtPtrs { const float* s[6]; };
__global__ void transpose_w6_kernel(WtPtrs ps, __half* __restrict__ Dbase) {
    __shared__ float tile[32][33];
    const float* s = ps.s[blockIdx.z];
    __half* d = Dbase + (long long)blockIdx.z * DD * DD;
    const int x = blockIdx.x * 32 + threadIdx.x;
    const int y0 = blockIdx.y * 32;
    #pragma unroll
    for (int i = threadIdx.y; i < 32; i += 8)
        tile[i][threadIdx.x] = s[(long long)(y0 + i) * DD + x];
    __syncthreads();
    const int xo = blockIdx.y * 32 + threadIdx.x;
    const int yo0 = blockIdx.x * 32;
    #pragma unroll
    for (int i = threadIdx.y; i < 32; i += 8)
        d[(long long)(yo0 + i) * DD + xo] = __float2half_rn(tile[threadIdx.x][i]);
}

// ---------------------------------------------------------------------------
// V transpose: fp32 [b][t][d] -> half [b][d][t]; 64t x 32d tiles, half2 writes
// ---------------------------------------------------------------------------
__global__ void __launch_bounds__(256) transpose_v_kernel(
    const float* __restrict__ V, __half* __restrict__ VT)
{
    __shared__ float sbuf[32 * 65];
    const int tid = threadIdx.x;
    const int d0 = blockIdx.x * 32;
    const int t0 = blockIdx.y * 64;
    const float* src = V + (long long)blockIdx.z * SS * DD;
    __half* dst = VT + (long long)blockIdx.z * DD * SS;

    #pragma unroll
    for (int i = 0; i < 8; i++) {
        const int idx = i * 256 + tid;
        const int r = idx >> 5, c = idx & 31;
        sbuf[c * 65 + r] = src[(long long)(t0 + r) * DD + d0 + c];
    }
    __syncthreads();
    #pragma unroll
    for (int i = 0; i < 4; i++) {
        const int idx = i * 256 + tid;
        const int drow = idx >> 5, tp = idx & 31;
        const float a = sbuf[drow * 65 + 2 * tp];
        const float b = sbuf[drow * 65 + 2 * tp + 1];
        *(__half2*)(dst + (long long)(d0 + drow) * SS + t0 + 2 * tp) =
            __floats2half2_rn(a, b);
    }
}

// ===========================================================================
// Multistage fp16 mma.sync NT GEMM (fp32 accumulate), ldmatrix fragments.
//   C[m,n] = epilogue( sum_k A[m,k] * B[n,k] )
// Block tile 128x128, 256 thr, 8 warps (4m x 2n), warp tile 32x64.
// DUAL: blockIdx.z selects pointer set 0/1. !DUAL: z batches via strides.
// EPI: 0 = +bias+relu (half out), 1 = +bias (half out),
//      2 = QK mask/scale (HALF out), 3 = plain (float out, streaming)
// Half outputs (EPI 0/1/2) are staged through smem for coalesced 16B stores.
// ===========================================================================
template<int EPI, bool DUAL>
__global__ void __launch_bounds__(256, 2) gemm_h(
    const __half* __restrict__ A0, const __half* __restrict__ B0,
    const float* __restrict__ bias0, void* __restrict__ C0,
    const __half* __restrict__ A1, const __half* __restrict__ B1,
    const float* __restrict__ bias1, void* __restrict__ C1,
    int K, int ldc, long long sA, long long sB, long long sC,
    const void* __restrict__ maskp)
{
    extern __shared__ __half smh[];
    const uint32_t sbase = smem_u32(smh);
    const int tid  = threadIdx.x;
    const int warp = tid >> 5;
    const int lane = tid & 31;
    const int wm = (warp >> 1) * 32;
    const int wn = (warp & 1) * 64;
    const int z = blockIdx.z;

    const __half* A; const __half* B; const float* bias; void* Cg;
    if (DUAL && z == 1) { A = A1; B = B1; bias = bias1; Cg = C1; }
    else {
        A = A0 + (long long)z * sA;
        B = B0 + (long long)z * sB;
        bias = bias0; Cg = C0;
    }
    const long long csoff = DUAL ? 0 : (long long)z * sC;

    const int bm = blockIdx.y * 128;
    const int bn = blockIdx.x * 128;

    const int lm_row = (lane & 7) + ((lane >> 3) & 1) * 8;
    const int lm_col = ((lane >> 4) & 1) * 8;
    uint32_t offA[2], offB[4];
    #pragma unroll
    for (int i = 0; i < 2; i++)
        offA[i] = (uint32_t)((wm + i * 16 + lm_row) * RS + lm_col);
    #pragma unroll
    for (int j2 = 0; j2 < 4; j2++)
        offB[j2] = (uint32_t)(TILE_HALVES + (wn + j2 * 16 + lm_row) * RS + lm_col);

    auto load_stage = [&](int t, int buf) {
        const __half* Abase = A + (long long)bm * K + t * TKS;
        const __half* Bbase = B + (long long)bn * K + t * TKS;
        const uint32_t s0 = sbase + (uint32_t)(buf * STAGE_HALVES) * 2u;
        #pragma unroll
        for (int i = 0; i < 4; i++) {
            const int c = tid + i * 256;
            const int m = c >> 3, kc = c & 7;
            CP_ASYNC16(s0 + (uint32_t)(m * RS + kc * 8) * 2u,
                       Abase + (long long)m * K + kc * 8);
            CP_ASYNC16(s0 + (uint32_t)(TILE_HALVES + m * RS + kc * 8) * 2u,
                       Bbase + (long long)m * K + kc * 8);
        }
    };

    float4 acc[2][8];
    #pragma unroll
    for (int i = 0; i < 2; i++)
        #pragma unroll
        for (int j = 0; j < 8; j++) acc[i][j] = make_float4(0.f, 0.f, 0.f, 0.f);

    const int T = K / TKS;

    load_stage(0, 0); CP_COMMIT();
    load_stage(1, 1); CP_COMMIT();

    for (int t = 0; t < T; t++) {
        const int buf = t % NSTAGE;
        CP_WAIT(1);
        __syncthreads();
        if (t + 2 < T) load_stage(t + 2, (t + 2) % NSTAGE);
        CP_COMMIT();

        const uint32_t base = sbase + (uint32_t)(buf * STAGE_HALVES) * 2u;

        #pragma unroll
        for (int ks = 0; ks < 4; ks++) {
            const uint32_t ck2 = (uint32_t)(ks * 16) * 2u;
            uint32_t af[2][4];
            LDMATRIX_X4(af[0][0], af[0][1], af[0][2], af[0][3], base + offA[0] * 2u + ck2);
            LDMATRIX_X4(af[1][0], af[1][1], af[1][2], af[1][3], base + offA[1] * 2u + ck2);
            #pragma unroll
            for (int j2 = 0; j2 < 4; j2++) {
                uint32_t m0, m1, m2, m3;
                LDMATRIX_X4(m0, m1, m2, m3, base + offB[j2] * 2u + ck2);
                const int j = j2 * 2;
                mma_f16(acc[0][j],     af[0][0], af[0][1], af[0][2], af[0][3], m0, m2);
                mma_f16(acc[1][j],     af[1][0], af[1][1], af[1][2], af[1][3], m0, m2);
                mma_f16(acc[0][j + 1], af[0][0], af[0][1], af[0][2], af[0][3], m1, m3);
                mma_f16(acc[1][j + 1], af[1][0], af[1][1], af[1][2], af[1][3], m1, m3);
            }
        }
    }

    // -------------------- Epilogue --------------------
    if (EPI == 3) {
        // fp32 output: streaming stores (never re-read; keep L2 for probs/vt)
        #pragma unroll
        for (int i = 0; i < 2; i++) {
            const int r0 = bm + wm + i * 16 + (lane >> 2);
            const int r1 = r0 + 8;
            #pragma unroll
            for (int j = 0; j < 8; j++) {
                const int c = bn + wn + j * 8 + (lane & 3) * 2;
                float* C = (float*)Cg + csoff;
                stwt_f2(C + (long long)r0 * ldc + c, make_float2(acc[i][j].x, acc[i][j].y));
                stwt_f2(C + (long long)r1 * ldc + c, make_float2(acc[i][j].z, acc[i][j].w));
            }
        }
    } else {
        // half output: stage tile in smem, then coalesced 16B row stores
        const int is_i32 = (EPI == 2) ? g_mask_is_i32 : 0;
        __syncthreads();                       // all smem reads done; reuse as staging
        #pragma unroll
        for (int i = 0; i < 2; i++) {
            const int rl0 = wm + i * 16 + (lane >> 2);
            const int rl1 = rl0 + 8;
            #pragma unroll
            for (int j = 0; j < 8; j++) {
                const int cl = wn + j * 8 + (lane & 3) * 2;
                float2 v0 = make_float2(acc[i][j].x, acc[i][j].y);
                float2 v1 = make_float2(acc[i][j].z, acc[i][j].w);
                if (EPI == 0 || EPI == 1) {
                    const float2 b = *(const float2*)(bias + bn + cl);
                    v0.x += b.x; v0.y += b.y;
                    v1.x += b.x; v1.y += b.y;
                    if (EPI == 0) {
                        v0.x = fmaxf(v0.x, 0.f); v0.y = fmaxf(v0.y, 0.f);
                        v1.x = fmaxf(v1.x, 0.f); v1.y = fmaxf(v1.y, 0.f);
                    }
                } else {   // EPI == 2
                    const long long base2 = (long long)z * SS * SS;
                    const long long i00 = base2 + (long long)(bm + rl0) * SS + bn + cl;
                    const long long i10 = base2 + (long long)(bm + rl1) * SS + bn + cl;
                    bool m00, m01, m10, m11;
                    if (is_i32) {
                        const int* mi = (const int*)maskp;
                        m00 = mi[i00] != 0; m01 = mi[i00 + 1] != 0;
                        m10 = mi[i10] != 0; m11 = mi[i10 + 1] != 0;
                    } else {
                        const unsigned char* mu = (const unsigned char*)maskp;
                        m00 = mu[i00] != 0; m01 = mu[i00 + 1] != 0;
                        m10 = mu[i10] != 0; m11 = mu[i10 + 1] != 0;
                    }
                    v0.x = m00 ? -60000.f : v0.x * INV_T;
                    v0.y = m01 ? -60000.f : v0.y * INV_T;
                    v1.x = m10 ? -60000.f : v1.x * INV_T;
                    v1.y = m11 ? -60000.f : v1.y * INV_T;
                }
                *(__half2*)(smh + rl0 * CS + cl) = __floats2half2_rn(v0.x, v0.y);
                *(__half2*)(smh + rl1 * CS + cl) = __floats2half2_rn(v1.x, v1.y);
            }
        }
        __syncthreads();
        __half* C = (__half*)Cg + csoff;
        #pragma unroll
        for (int p = 0; p < 8; p++) {
            const int r = p * 16 + (tid >> 4);
            const int ch = (tid & 15) * 8;
            *(uint4*)(C + (long long)(bm + r) * ldc + bn + ch) =
                *(const uint4*)(smh + r * CS + ch);
        }
    }
}

// ---------------------------------------------------------------------------
// Block reduction (sum)
// ---------------------------------------------------------------------------
__device__ __forceinline__ float blockReduceSum(float v, float* sh) {
    #pragma unroll
    for (int o = 16; o > 0; o >>= 1) v += __shfl_xor_sync(0xffffffffu, v, o);
    __syncthreads();
    if ((threadIdx.x & 31) == 0) sh[threadIdx.x >> 5] = v;
    __syncthreads();
    if (threadIdx.x < 32) {
        v = (threadIdx.x < (blockDim.x >> 5)) ? sh[threadIdx.x] : 0.0f;
        #pragma unroll
        for (int o = 16; o > 0; o >>= 1) v += __shfl_xor_sync(0xffffffffu, v, o);
        if (threadIdx.x == 0) sh[0] = v;
    }
    __syncthreads();
    return sh[0];
}

// ---------------------------------------------------------------------------
// LayerNorm + ReLU, dual chain in one launch (q rows then k rows)
// ---------------------------------------------------------------------------
__global__ void ln_relu_h2_kernel(const __half* __restrict__ X0, __half* __restrict__ Y0,
                                  const float* __restrict__ g0, const float* __restrict__ b0,
                                  const __half* __restrict__ X1, __half* __restrict__ Y1,
                                  const float* __restrict__ g1, const float* __restrict__ b1)
{
    __shared__ float sh[32];
    long long row = blockIdx.x;
    const __half* X; __half* Y; const float* g; const float* beta;
    if (row < MFULL) { X = X0; Y = Y0; g = g0; beta = b0; }
    else { row -= MFULL; X = X1; Y = Y1; g = g1; beta = b1; }
    const __half* x = X + row * DD;
    const int t = threadIdx.x;

    const __half2 h0 = *(const __half2*)(x + t * 4);
    const __half2 h1 = *(const __half2*)(x + t * 4 + 2);
    const float2 f0 = __half22float2(h0);
    const float2 f1 = __half22float2(h1);
    float s  = f0.x + f0.y + f1.x + f1.y;
    float sq = f0.x * f0.x + f0.y * f0.y + f1.x * f1.x + f1.y * f1.y;
    s  = blockReduceSum(s, sh);
    sq = blockReduceSum(sq, sh);
    const float mu  = s * (1.0f / DD);
    const float var = sq * (1.0f / DD) - mu * mu;
    const float r = rsqrtf(var + LN_EPS);

    const float4 gv = *(const float4*)(g + t * 4);
    const float4 bv = *(const float4*)(beta + t * 4);
    float y0 = fmaxf((f0.x - mu) * r * gv.x + bv.x, 0.0f);
    float y1 = fmaxf((f0.y - mu) * r * gv.y + bv.y, 0.0f);
    float y2 = fmaxf((f1.x - mu) * r * gv.z + bv.z, 0.0f);
    float y3 = fmaxf((f1.y - mu) * r * gv.w + bv.w, 0.0f);
    *(__half2*)(Y + row * DD + t * 4)     = __floats2half2_rn(y0, y1);
    *(__half2*)(Y + row * DD + t * 4 + 2) = __floats2half2_rn(y2, y3);
}

// ---------------------------------------------------------------------------
// Negated softmax (no max pass — logits bounded, masked = -60000 -> exp = 0):
// reads half logits (uint4), writes fp32 attn (streaming) + half probs
// ---------------------------------------------------------------------------
__global__ void softmax_neg_kernel(__half* __restrict__ PH, float* __restrict__ P) {
    __shared__ float sh[32];
    __half* ph = PH + (long long)blockIdx.x * SS;
    float* p = P + (long long)blockIdx.x * SS;
    const int t = threadIdx.x;

    const uint4 raw = *(const uint4*)(ph + t * 8);
    const __half2* hp = (const __half2*)&raw;
    const float2 a = __half22float2(hp[0]);
    const float2 b = __half22float2(hp[1]);
    const float2 c = __half22float2(hp[2]);
    const float2 d = __half22float2(hp[3]);
    float x[8] = {a.x, a.y, b.x, b.y, c.x, c.y, d.x, d.y};

    float e[8], s = 0.f;
    #pragma unroll
    for (int i = 0; i < 8; i++) { e[i] = __expf(x[i]); s += e[i]; }
    s = blockReduceSum(s, sh);
    const float inv = -1.0f / s;

    #pragma unroll
    for (int i = 0; i < 8; i++) e[i] *= inv;
    stwt_f4(p + t * 8,     make_float4(e[0], e[1], e[2], e[3]));
    stwt_f4(p + t * 8 + 4, make_float4(e[4], e[5], e[6], e[7]));
    uint4 outh;
    __half2* ohp = (__half2*)&outh;
    ohp[0] = __floats2half2_rn(e[0], e[1]);
    ohp[1] = __floats2half2_rn(e[2], e[3]);
    ohp[2] = __floats2half2_rn(e[4], e[5]);
    ohp[3] = __floats2half2_rn(e[6], e[7]);
    *(uint4*)(ph + t * 8) = outh;
}

// ---------------------------------------------------------------------------
// Launch
// ---------------------------------------------------------------------------
extern "C" void kernel_launch(void* const* d_in, const int* in_sizes, int n_in,
                              void* d_out, int out_size)
{
    const float* q   = (const float*)d_in[0];
    const float* k   = (const float*)d_in[1];
    const float* v   = (const float*)d_in[2];
    const void*  mask = d_in[3];
    const float* qw1 = (const float*)d_in[4];
    const float* qw2 = (const float*)d_in[5];
    const float* qw3 = (const float*)d_in[6];
    const float* kw1 = (const float*)d_in[7];
    const float* kw2 = (const float*)d_in[8];
    const float* kw3 = (const float*)d_in[9];
    const float* qb1 = (const float*)d_in[10];
    const float* qb2 = (const float*)d_in[11];
    const float* qb3 = (const float*)d_in[12];
    const float* kb1 = (const float*)d_in[13];
    const float* kb2 = (const float*)d_in[14];
    const float* kb3 = (const float*)d_in[15];
    const float* q_ln_b = (const float*)d_in[16];
    const float* k_ln_b = (const float*)d_in[17];
    const float* q_ln_g = (const float*)d_in[18];
    const float* k_ln_g = (const float*)d_in[19];

    float* out  = (float*)d_out;                              // [B,S,D]
    float* attn = out + (long long)BB * SS * DD;              // [B,S,S]

    __half *qh, *kh, *t1, *t2, *t3, *t4, *dq, *dk, *wt, *vt, *ah;
    cudaGetSymbolAddress((void**)&qh, g_qh);
    cudaGetSymbolAddress((void**)&kh, g_kh);
    cudaGetSymbolAddress((void**)&t1, g_t1);
    cudaGetSymbolAddress((void**)&t2, g_t2);
    cudaGetSymbolAddress((void**)&t3, g_t3);
    cudaGetSymbolAddress((void**)&t4, g_t4);
    cudaGetSymbolAddress((void**)&dq, g_dq);
    cudaGetSymbolAddress((void**)&dk, g_dk);
    cudaGetSymbolAddress((void**)&wt, g_wt);
    cudaGetSymbolAddress((void**)&vt, g_vt);
    cudaGetSymbolAddress((void**)&ah, g_ah);

    const size_t shm = GEMM_SMEM_BYTES;
    cudaFuncSetAttribute(gemm_h<0, true >, cudaFuncAttributeMaxDynamicSharedMemorySize, shm);
    cudaFuncSetAttribute(gemm_h<1, true >, cudaFuncAttributeMaxDynamicSharedMemorySize, shm);
    cudaFuncSetAttribute(gemm_h<2, false>, cudaFuncAttributeMaxDynamicSharedMemorySize, shm);
    cudaFuncSetAttribute(gemm_h<3, false>, cudaFuncAttributeMaxDynamicSharedMemorySize, shm);

    detect_mask_kernel<<<1, 256>>>((const unsigned char*)mask);

    // fp32 -> fp16 inputs (q and k in one launch; 8 elems/thread)
    const long long n8 = (long long)MFULL * DD / 8;
    convert2_h_kernel<<<(int)((2 * n8 + 255) / 256), 256>>>(q, qh, k, kh, n8);

    // All 6 weight transposes in one launch
    WtPtrs wp;
    wp.s[0] = qw1; wp.s[1] = qw2; wp.s[2] = qw3;
    wp.s[3] = kw1; wp.s[4] = kw2; wp.s[5] = kw3;
    transpose_w6_kernel<<<dim3(16, 16, 6), dim3(32, 8)>>>(wp, wt);
    __half* wtq1 = wt + 0LL * DD * DD; __half* wtq2 = wt + 1LL * DD * DD;
    __half* wtq3 = wt + 2LL * DD * DD; __half* wtk1 = wt + 3LL * DD * DD;
    __half* wtk2 = wt + 4LL * DD * DD; __half* wtk3 = wt + 5LL * DD * DD;

    // V transpose (half2-packed writes)
    transpose_v_kernel<<<dim3(DD / 32, SS / 64, BB), 256>>>(v, vt);

    // ---- dual MLP chains (q: z=0, k: z=1) ----
    const dim3 gMLP(DD / 128, MFULL / 128, 2);   // (4, 128, 2)
    gemm_h<0, true><<<gMLP, 256, shm>>>(qh, wtq1, qb1, t1, kh, wtk1, kb1, t3,
                                        DD, DD, 0, 0, 0, nullptr);
    gemm_h<1, true><<<gMLP, 256, shm>>>(t1, wtq2, qb2, t2, t3, wtk2, kb2, t4,
                                        DD, DD, 0, 0, 0, nullptr);
    ln_relu_h2_kernel<<<2 * MFULL, 128>>>(t2, t1, q_ln_g, q_ln_b,
                                          t4, t3, k_ln_g, k_ln_b);
    gemm_h<1, true><<<gMLP, 256, shm>>>(t1, wtq3, qb3, dq, t3, wtk3, kb3, dk,
                                        DD, DD, 0, 0, 0, nullptr);

    // ---- attention ----
    gemm_h<2, false><<<dim3(SS / 128, SS / 128, BB), 256, shm>>>(
        dq, dk, nullptr, ah, nullptr, nullptr, nullptr, nullptr,
        DD, SS, (long long)SS * DD, (long long)SS * DD, (long long)SS * SS, mask);
    softmax_neg_kernel<<<MFULL, 256>>>(ah, attn);
    gemm_h<3, false><<<dim3(DD / 128, SS / 128, BB), 256, shm>>>(
        ah, vt, nullptr, out, nullptr, nullptr, nullptr, nullptr,
        SS, DD, (long long)SS * SS, (long long)DD * SS, (long long)SS * DD, nullptr);
}